// round 2
// baseline (speedup 1.0000x reference)
#include <cuda_runtime.h>
#include <cuda_bf16.h>
#include <cstdint>

// Problem constants
#define BATCH 4
#define NPTS  16384
#define KNN   16
#define CIN   64
#define DREL  64
#define CMID  128
#define COUT  128

#define FT_STRIDE 20               // padded k-stride for fT[c][k] (float4-aligned, 80B)
#define GROUPS    ((BATCH * NPTS) / 8)   // 8192 groups of 8 consecutive points

// Scratch: transposed features xt[b][n][c]  (16 MB)
__device__ float g_xt[BATCH * NPTS * CIN];

// ---------------------------------------------------------------------------
// Transpose x[B][64][N] -> g_xt[B][N][64]
// ---------------------------------------------------------------------------
__global__ void transpose_x_kernel(const float* __restrict__ x) {
    __shared__ float tile[32][33];
    const int b  = blockIdx.z;
    const int c0 = blockIdx.y * 32;
    const int n0 = blockIdx.x * 32;
    const int tx = threadIdx.x, ty = threadIdx.y;   // (32, 8)

    const float* xb = x + (size_t)b * CIN * NPTS;
#pragma unroll
    for (int i = 0; i < 4; ++i)
        tile[ty + 8 * i][tx] = xb[(size_t)(c0 + ty + 8 * i) * NPTS + n0 + tx];
    __syncthreads();
    float* xo = g_xt + ((size_t)b * NPTS + n0) * CIN;
#pragma unroll
    for (int i = 0; i < 4; ++i)
        xo[(size_t)(ty + 8 * i) * CIN + c0 + tx] = tile[tx][ty + 8 * i];
}

// ---------------------------------------------------------------------------
// Fused RandLA-Net attention kernel.
// 256 threads = 8 warps per CTA, 1 CTA per SM (SMEM-limited), persistent over
// point-groups. Warp w of group g handles point p = g*8 + w.
//
// SMEM layout (floats):
//   sWatt  [128*128]   attention weights, row-major [c][o]
//   sWglob [128*128]   global weights,    row-major [c][o]
//   sWrel  [10*64]
//   sbrel  [64]
//   sbglob [128]
//   fT     [8 warps][128 * FT_STRIDE]   f transposed: fT[c*20 + k]
//   sAgg   [8][128]
//   sOut   [8][128]
// ---------------------------------------------------------------------------
#define SMEM_FLOATS (CMID*CMID*2 + 10*DREL + DREL + COUT + 8*CMID*FT_STRIDE + 8*CMID + 8*CMID)
#define SMEM_BYTES  (SMEM_FLOATS * 4)

__global__ __launch_bounds__(256, 1)
void randlanet_fused_kernel(const float* __restrict__ pos,
                            const int*   __restrict__ nidx,
                            const float* __restrict__ Wrel,
                            const float* __restrict__ brel,
                            const float* __restrict__ Watt,
                            const float* __restrict__ Wglob,
                            const float* __restrict__ bglob,
                            float*       __restrict__ out) {
    extern __shared__ float smem[];
    float* sWatt  = smem;
    float* sWglob = sWatt  + CMID * CMID;
    float* sWrel  = sWglob + CMID * CMID;
    float* sbrel  = sWrel  + 10 * DREL;
    float* sbglob = sbrel  + DREL;
    float* sfT    = sbglob + COUT;
    float* sAgg   = sfT    + 8 * CMID * FT_STRIDE;
    float* sOut   = sAgg   + 8 * CMID;

    const int tid  = threadIdx.x;
    const int warp = tid >> 5;
    const int lane = tid & 31;

    // Cooperative weight load
    for (int i = tid; i < CMID * CMID; i += 256) sWatt[i]  = Watt[i];
    for (int i = tid; i < CMID * CMID; i += 256) sWglob[i] = Wglob[i];
    for (int i = tid; i < 10 * DREL;   i += 256) sWrel[i]  = Wrel[i];
    if (tid < DREL) sbrel[tid]  = brel[tid];
    if (tid < COUT) sbglob[tid] = bglob[tid];
    __syncthreads();

    float* fT = sfT + warp * CMID * FT_STRIDE;

    for (int g = blockIdx.x; g < GROUPS; g += gridDim.x) {
        const int p0 = g * 8;
        const int p  = p0 + warp;          // global point index
        const int b  = p >> 14;            // NPTS = 16384
        const int n  = p & (NPTS - 1);

        const float* posB = pos + (size_t)b * NPTS * 3;
        const float cx = posB[n * 3 + 0];
        const float cy = posB[n * 3 + 1];
        const float cz = posB[n * 3 + 2];

        // lanes 0..15 hold one neighbor index each
        int myidx = 0;
        if (lane < KNN) myidx = nidx[(size_t)p * KNN + lane];

        // ---- Build f (rel-pos MLP + gathered features) into fT[c][k] ----
#pragma unroll 1
        for (int k = 0; k < KNN; ++k) {
            const int id = __shfl_sync(0xffffffffu, myidx, k);
            const float nx = posB[id * 3 + 0];
            const float ny = posB[id * 3 + 1];
            const float nz = posB[id * 3 + 2];
            const float rx = nx - cx, ry = ny - cy, rz = nz - cz;
            const float d  = sqrtf(rx * rx + ry * ry + rz * rz);
            float enc[10] = {cx, cy, cz, nx, ny, nz, rx, ry, rz, d};

            float r0 = sbrel[lane];
            float r1 = sbrel[lane + 32];
#pragma unroll
            for (int e = 0; e < 10; ++e) {
                r0 = fmaf(enc[e], sWrel[e * DREL + lane],      r0);
                r1 = fmaf(enc[e], sWrel[e * DREL + lane + 32], r1);
            }
            fT[(lane)      * FT_STRIDE + k] = fmaxf(r0, 0.0f);
            fT[(lane + 32) * FT_STRIDE + k] = fmaxf(r1, 0.0f);

            const float* xr = g_xt + ((size_t)b * NPTS + id) * CIN;
            fT[(64 + lane) * FT_STRIDE + k] = xr[lane];
            fT[(96 + lane) * FT_STRIDE + k] = xr[lane + 32];
        }
        __syncwarp();

        // ---- scores[k][o] = sum_c f[k][c] * Watt[c][o] ----
        // lane owns output channels o = 4*lane + j, j=0..3, for all k
        float acc[KNN][4];
#pragma unroll
        for (int k = 0; k < KNN; ++k)
#pragma unroll
            for (int j = 0; j < 4; ++j) acc[k][j] = 0.0f;

#pragma unroll 1
        for (int c = 0; c < CMID; ++c) {
            const float4 w = *(const float4*)(sWatt + c * CMID + 4 * lane);
            const float* fc = fT + c * FT_STRIDE;
            const float4 fa = *(const float4*)(fc);
            const float4 fb = *(const float4*)(fc + 4);
            const float4 fg = *(const float4*)(fc + 8);
            const float4 fd = *(const float4*)(fc + 12);
            const float fk[KNN] = {fa.x, fa.y, fa.z, fa.w,
                                   fb.x, fb.y, fb.z, fb.w,
                                   fg.x, fg.y, fg.z, fg.w,
                                   fd.x, fd.y, fd.z, fd.w};
#pragma unroll
            for (int k = 0; k < KNN; ++k) {
                acc[k][0] = fmaf(fk[k], w.x, acc[k][0]);
                acc[k][1] = fmaf(fk[k], w.y, acc[k][1]);
                acc[k][2] = fmaf(fk[k], w.z, acc[k][2]);
                acc[k][3] = fmaf(fk[k], w.w, acc[k][3]);
            }
        }

        // ---- softmax over k (lane-local) + aggregation ----
#pragma unroll
        for (int j = 0; j < 4; ++j) {
            float m = acc[0][j];
#pragma unroll
            for (int k = 1; k < KNN; ++k) m = fmaxf(m, acc[k][j]);
            float s = 0.0f;
#pragma unroll
            for (int k = 0; k < KNN; ++k) {
                const float e = __expf(acc[k][j] - m);
                acc[k][j] = e;
                s += e;
            }
            const float* fr = fT + (4 * lane + j) * FT_STRIDE;
            const float4 g0 = *(const float4*)(fr);
            const float4 g1 = *(const float4*)(fr + 4);
            const float4 g2 = *(const float4*)(fr + 8);
            const float4 g3 = *(const float4*)(fr + 12);
            const float fk2[KNN] = {g0.x, g0.y, g0.z, g0.w,
                                    g1.x, g1.y, g1.z, g1.w,
                                    g2.x, g2.y, g2.z, g2.w,
                                    g3.x, g3.y, g3.z, g3.w};
            float a = 0.0f;
#pragma unroll
            for (int k = 0; k < KNN; ++k) a = fmaf(acc[k][j], fk2[k], a);
            sAgg[warp * CMID + 4 * lane + j] = a / s;
        }
        __syncwarp();

        // ---- out[o] = relu(sum_c agg[c] * Wglob[c][o] + bglob[o]) ----
        const float* aggw = sAgg + warp * CMID;
        float4 oc = *(const float4*)(sbglob + 4 * lane);
#pragma unroll 1
        for (int c = 0; c < CMID; ++c) {
            const float av = aggw[c];
            const float4 w = *(const float4*)(sWglob + c * CMID + 4 * lane);
            oc.x = fmaf(av, w.x, oc.x);
            oc.y = fmaf(av, w.y, oc.y);
            oc.z = fmaf(av, w.z, oc.z);
            oc.w = fmaf(av, w.w, oc.w);
        }
        oc.x = fmaxf(oc.x, 0.0f);
        oc.y = fmaxf(oc.y, 0.0f);
        oc.z = fmaxf(oc.z, 0.0f);
        oc.w = fmaxf(oc.w, 0.0f);
        *(float4*)(sOut + warp * CMID + 4 * lane) = oc;

        __syncthreads();

        // ---- coalesced staged write: out[b][o][n0..n0+7] ----
        {
            const int o  = tid >> 1;
            const int nn = (tid & 1) * 4;
            const int bb = p0 >> 14;
            const int n0 = p0 & (NPTS - 1);
            float4 v;
            v.x = sOut[(nn + 0) * CMID + o];
            v.y = sOut[(nn + 1) * CMID + o];
            v.z = sOut[(nn + 2) * CMID + o];
            v.w = sOut[(nn + 3) * CMID + o];
            *(float4*)(out + ((size_t)(bb * COUT + o)) * NPTS + n0 + nn) = v;
        }
        __syncthreads();
    }
}

// ---------------------------------------------------------------------------
extern "C" void kernel_launch(void* const* d_in, const int* in_sizes, int n_in,
                              void* d_out, int out_size) {
    const float* x     = (const float*)d_in[0];
    const float* pos   = (const float*)d_in[1];
    const int*   nidx  = (const int*)  d_in[2];
    const float* Wrel  = (const float*)d_in[3];
    const float* brel  = (const float*)d_in[4];
    const float* Watt  = (const float*)d_in[5];
    const float* Wglob = (const float*)d_in[6];
    const float* bglob = (const float*)d_in[7];
    float*       out   = (float*)d_out;

    // transpose x -> g_xt
    transpose_x_kernel<<<dim3(NPTS / 32, CIN / 32, BATCH), dim3(32, 8)>>>(x);

    cudaFuncSetAttribute(randlanet_fused_kernel,
                         cudaFuncAttributeMaxDynamicSharedMemorySize, SMEM_BYTES);
    randlanet_fused_kernel<<<148, 256, SMEM_BYTES>>>(pos, nidx, Wrel, brel,
                                                     Watt, Wglob, bglob, out);
}

// round 7
// speedup vs baseline: 1.3981x; 1.3981x over previous
#include <cuda_runtime.h>
#include <cuda_bf16.h>
#include <cstdint>

// Problem constants
#define BATCH 4
#define NPTS  16384
#define KNN   16
#define CIN   64
#define DREL  64
#define CMID  128
#define COUT  128
#define GROUPS ((BATCH * NPTS) / 8)   // 8192 groups of 8 points
#define LOG2E 1.4426950408889634f

// ---------------------------------------------------------------------------
// SMEM layout (bytes)
//   Fhi : [128 c rows][128 pk cols] bf16, row stride 272B (16B-aligned pad;
//         17x16B stride => ldmatrix row addresses hit distinct 16B banks)
//   Flo : same
//   Wglob fp32 [128][128]
//   Wrel fp32 [10][64], brel[64], bglob[128]
//   sAgg [8 pts][128], sOut [8 pts][128]
// ---------------------------------------------------------------------------
#define F_ROWSTRIDE 272
#define F_TILE      (128 * F_ROWSTRIDE + 64)     // 34880
#define OFF_FHI     0
#define OFF_FLO     (OFF_FHI + F_TILE)
#define OFF_WGLOB   (OFF_FLO + F_TILE)           // 69760
#define OFF_WREL    (OFF_WGLOB + 65536)
#define OFF_BREL    (OFF_WREL + 2560)
#define OFF_BGLOB   (OFF_BREL + 256)
#define OFF_AGG     (OFF_BGLOB + 512)
#define OFF_SOUT    (OFF_AGG + 4096)
#define SMEM_BYTES  (OFF_SOUT + 4096)            // 146816

// Scratch: transposed features xt[b][n][c]  (16 MB)
__device__ float g_xt[BATCH * NPTS * CIN];

// ---------------------------------------------------------------------------
static __device__ __forceinline__ uint32_t smem_u32(const void* p) {
    uint32_t a;
    asm("{ .reg .u64 t; cvta.to.shared.u64 t, %1; cvt.u32.u64 %0, t; }" : "=r"(a) : "l"(p));
    return a;
}

// Row start (byte offset within a tile) for channel row c.
// NO intra-tile swizzle: row data is 256B inside a 272B stride; the previous
// group-swizzle overflowed rows into each other (rel_err 4e-2 root cause).
static __device__ __forceinline__ uint32_t frow(int c) {
    return (uint32_t)(c * F_ROWSTRIDE);
}

static __device__ __forceinline__ uint32_t pack_bf16x2(float v0, float v1) {
    __nv_bfloat162 h = __floats2bfloat162_rn(v0, v1);   // .x=v0 (low 16b)
    return *(uint32_t*)&h;
}

// fast 2^y : magic-rounding + degree-5 poly, FMA/ALU pipes only (no MUFU)
static __device__ __forceinline__ float fast_exp2(float y) {
    y = fmaxf(y, -80.0f);
    const float t = y + 12582912.0f;                    // 1.5 * 2^23
    const int   i = __float_as_int(t);
    const float f = y - (t - 12582912.0f);              // [-0.5, 0.5]
    float p = 0.00133335581f;
    p = fmaf(p, f, 0.00961812911f);
    p = fmaf(p, f, 0.05550410866f);
    p = fmaf(p, f, 0.24022650696f);
    p = fmaf(p, f, 0.69314718056f);
    p = fmaf(p, f, 1.0f);
    return __int_as_float(__float_as_int(p) + (i << 23));
}

#define MMA_BF16(D, A, B0, B1)                                                  \
    asm volatile("mma.sync.aligned.m16n8k16.row.col.f32.bf16.bf16.f32 "         \
                 "{%0,%1,%2,%3}, {%4,%5,%6,%7}, {%8,%9}, {%0,%1,%2,%3};"        \
                 : "+f"((D)[0]), "+f"((D)[1]), "+f"((D)[2]), "+f"((D)[3])       \
                 : "r"((A)[0]), "r"((A)[1]), "r"((A)[2]), "r"((A)[3]),          \
                   "r"(B0), "r"(B1))

#define LDSM_X2_T(R0, R1, ADDR)                                                 \
    asm volatile("ldmatrix.sync.aligned.m8n8.x2.trans.shared.b16 {%0,%1}, [%2];"\
                 : "=r"(R0), "=r"(R1) : "r"(ADDR))

#define LDSM_X4(R, ADDR)                                                        \
    asm volatile("ldmatrix.sync.aligned.m8n8.x4.shared.b16 {%0,%1,%2,%3}, [%4];"\
                 : "=r"((R)[0]), "=r"((R)[1]), "=r"((R)[2]), "=r"((R)[3])       \
                 : "r"(ADDR))

// ---------------------------------------------------------------------------
// Transpose x[B][64][N] -> g_xt[B][N][64]
// ---------------------------------------------------------------------------
__global__ void transpose_x_kernel(const float* __restrict__ x) {
    __shared__ float tile[32][33];
    const int b  = blockIdx.z;
    const int c0 = blockIdx.y * 32;
    const int n0 = blockIdx.x * 32;
    const int tx = threadIdx.x, ty = threadIdx.y;   // (32, 8)

    const float* xb = x + (size_t)b * CIN * NPTS;
#pragma unroll
    for (int i = 0; i < 4; ++i)
        tile[ty + 8 * i][tx] = xb[(size_t)(c0 + ty + 8 * i) * NPTS + n0 + tx];
    __syncthreads();
    float* xo = g_xt + ((size_t)b * NPTS + n0) * CIN;
#pragma unroll
    for (int i = 0; i < 4; ++i)
        xo[(size_t)(ty + 8 * i) * CIN + c0 + tx] = tile[tx][ty + 8 * i];
}

// ---------------------------------------------------------------------------
// Fused kernel. 148 persistent CTAs x 256 threads (8 warps).
// Warp w owns output-channel chunk o = 16w..16w+15 (W fragments in registers,
// pre-scaled by log2e and split bf16 hi/lo). Per group of 8 points:
//   phase 1: warp w builds f for point w into SMEM F tiles (bf16 hi/lo)
//   phase 2: per point: 48 mma.sync (3-matrix hi/lo) -> scores fragment;
//            lane-local+shfl softmax over k (exp2 via FMA poly);
//            agg with f re-loaded in matching fragment layout -> sAgg
//   phase 3: fp32 SIMT out-GEMM + coalesced staged store
// ---------------------------------------------------------------------------
__global__ __launch_bounds__(256, 1)
void randlanet_mma_kernel(const float* __restrict__ pos,
                          const int*   __restrict__ nidx,
                          const float* __restrict__ Wrel,
                          const float* __restrict__ brel,
                          const float* __restrict__ Watt,
                          const float* __restrict__ Wglob,
                          const float* __restrict__ bglob,
                          float*       __restrict__ out) {
    extern __shared__ char smem[];
    char*  sFhi   = smem + OFF_FHI;
    char*  sFlo   = smem + OFF_FLO;
    float* sWglob = (float*)(smem + OFF_WGLOB);
    float* sWrel  = (float*)(smem + OFF_WREL);
    float* sbrel  = (float*)(smem + OFF_BREL);
    float* sbglob = (float*)(smem + OFF_BGLOB);
    float* sAgg   = (float*)(smem + OFF_AGG);
    float* sOut   = (float*)(smem + OFF_SOUT);

    const uint32_t uFhi = smem_u32(sFhi);
    const uint32_t uFlo = smem_u32(sFlo);

    const int tid  = threadIdx.x;
    const int warp = tid >> 5;
    const int lane = tid & 31;
    const int gid  = lane >> 2;     // 0..7
    const int qid  = lane & 3;      // 0..3

    // ---- cooperative load of fp32 weights ----
    for (int i = tid; i < CMID * CMID; i += 256) sWglob[i] = Wglob[i];
    for (int i = tid; i < 10 * DREL;   i += 256) sWrel[i]  = Wrel[i];
    if (tid < DREL) sbrel[tid]  = brel[tid];
    if (tid < COUT) sbglob[tid] = bglob[tid];

    // ---- W_att A-fragments, register resident, scaled by log2e ----
    // A chunk for warp w: rows o = 16w.., cols c (k-dim). reg r:
    //   o = 16w + gid + (r&1)*8 ; c = 16cc + 2*qid + (r>>1)*8, pair (c, c+1)
    uint32_t Ahi[8][4], Alo[8][4];
#pragma unroll
    for (int cc = 0; cc < 8; ++cc) {
#pragma unroll
        for (int r = 0; r < 4; ++r) {
            const int o = 16 * warp + gid + (r & 1) * 8;
            const int c = 16 * cc + 2 * qid + (r >> 1) * 8;
            const float v0 = Watt[c * CMID + o] * LOG2E;
            const float v1 = Watt[(c + 1) * CMID + o] * LOG2E;
            const __nv_bfloat16 h0 = __float2bfloat16(v0);
            const __nv_bfloat16 h1 = __float2bfloat16(v1);
            Ahi[cc][r] = pack_bf16x2(__bfloat162float(h0), __bfloat162float(h1));
            // lo parts (exact residuals re-rounded)
            Alo[cc][r] = pack_bf16x2(v0 - __bfloat162float(h0),
                                     v1 - __bfloat162float(h1));
        }
    }
    __syncthreads();

    // per-lane ldmatrix base addresses
    uint32_t rowHi[8], rowLo[8];
#pragma unroll
    for (int cc = 0; cc < 8; ++cc) {
        const uint32_t fo = frow(16 * cc + (lane & 15));
        rowHi[cc] = uFhi + fo;
        rowLo[cc] = uFlo + fo;
    }
    const uint32_t aggOff = frow(16 * warp + (lane & 15)) + ((lane & 16) ? 16u : 0u);
    const uint32_t aggHiB = uFhi + aggOff;
    const uint32_t aggLoB = uFlo + aggOff;

    for (int g = blockIdx.x; g < GROUPS; g += gridDim.x) {
        const int p0 = g * 8;
        const int p  = p0 + warp;
        const int b  = p >> 14;            // NPTS = 16384
        const int n  = p & (NPTS - 1);

        // ================= phase 1: build f for this warp's point =========
        const float* posB = pos + (size_t)b * NPTS * 3;
        const float cx = posB[n * 3 + 0];
        const float cy = posB[n * 3 + 1];
        const float cz = posB[n * 3 + 2];
        int myidx = 0;
        if (lane < KNN) myidx = nidx[(size_t)p * KNN + lane];

#pragma unroll 1
        for (int k2 = 0; k2 < KNN; k2 += 2) {
            const int id0 = __shfl_sync(0xffffffffu, myidx, k2);
            const int id1 = __shfl_sync(0xffffffffu, myidx, k2 + 1);
            float v0[4], v1[4];   // channels: lane, lane+32, 64+lane, 96+lane
#pragma unroll
            for (int s = 0; s < 2; ++s) {
                const int id = s ? id1 : id0;
                const float nx = posB[id * 3 + 0];
                const float ny = posB[id * 3 + 1];
                const float nz = posB[id * 3 + 2];
                const float rx = nx - cx, ry = ny - cy, rz = nz - cz;
                const float d  = sqrtf(rx * rx + ry * ry + rz * rz);
                const float enc[10] = {cx, cy, cz, nx, ny, nz, rx, ry, rz, d};
                float r0 = sbrel[lane];
                float r1 = sbrel[lane + 32];
#pragma unroll
                for (int e = 0; e < 10; ++e) {
                    r0 = fmaf(enc[e], sWrel[e * DREL + lane],      r0);
                    r1 = fmaf(enc[e], sWrel[e * DREL + lane + 32], r1);
                }
                const float* xr = g_xt + ((size_t)b * NPTS + id) * CIN;
                float* v = s ? v1 : v0;
                v[0] = fmaxf(r0, 0.0f);
                v[1] = fmaxf(r1, 0.0f);
                v[2] = xr[lane];
                v[3] = xr[lane + 32];
            }
            const uint32_t pkb = (uint32_t)(warp * KNN + k2) * 2;  // byte col
            const int crow[4] = {lane, lane + 32, 64 + lane, 96 + lane};
#pragma unroll
            for (int s = 0; s < 4; ++s) {
                const uint32_t fo = frow(crow[s]) + pkb;
                const __nv_bfloat16 h0 = __float2bfloat16(v0[s]);
                const __nv_bfloat16 h1 = __float2bfloat16(v1[s]);
                *(uint32_t*)(sFhi + fo) =
                    pack_bf16x2(__bfloat162float(h0), __bfloat162float(h1));
                *(uint32_t*)(sFlo + fo) =
                    pack_bf16x2(v0[s] - __bfloat162float(h0),
                                v1[s] - __bfloat162float(h1));
            }
        }
        __syncthreads();

        // ================= phase 2: MMA scores + softmax + agg ============
#pragma unroll 1
        for (int pt = 0; pt < 8; ++pt) {
            const uint32_t colb = (uint32_t)pt * 32;
            float d0[4] = {0.f, 0.f, 0.f, 0.f};   // pk half 0
            float d1[4] = {0.f, 0.f, 0.f, 0.f};   // pk half 1
#pragma unroll
            for (int cc = 0; cc < 8; ++cc) {
                uint32_t bh0, bh1, bl0, bl1;
                LDSM_X2_T(bh0, bh1, rowHi[cc] + colb);
                LDSM_X2_T(bl0, bl1, rowLo[cc] + colb);
                MMA_BF16(d0, Ahi[cc], bh0, bh1);
                MMA_BF16(d0, Ahi[cc], bl0, bl1);
                MMA_BF16(d0, Alo[cc], bh0, bh1);
                LDSM_X2_T(bh0, bh1, rowHi[cc] + colb + 16);
                LDSM_X2_T(bl0, bl1, rowLo[cc] + colb + 16);
                MMA_BF16(d1, Ahi[cc], bh0, bh1);
                MMA_BF16(d1, Ahi[cc], bl0, bl1);
                MMA_BF16(d1, Alo[cc], bh0, bh1);
            }

            // rows: A -> channel 16w+gid, B -> channel 16w+gid+8
            // vA = scores at pk {2q, 2q+1, 8+2q, 8+2q+1} (log2 domain)
            float vA[4] = {d0[0], d0[1], d1[0], d1[1]};
            float vB[4] = {d0[2], d0[3], d1[2], d1[3]};

            float mA = fmaxf(fmaxf(vA[0], vA[1]), fmaxf(vA[2], vA[3]));
            float mB = fmaxf(fmaxf(vB[0], vB[1]), fmaxf(vB[2], vB[3]));
            mA = fmaxf(mA, __shfl_xor_sync(0xffffffffu, mA, 1));
            mA = fmaxf(mA, __shfl_xor_sync(0xffffffffu, mA, 2));
            mB = fmaxf(mB, __shfl_xor_sync(0xffffffffu, mB, 1));
            mB = fmaxf(mB, __shfl_xor_sync(0xffffffffu, mB, 2));

            float sA = 0.f, sB = 0.f;
#pragma unroll
            for (int j = 0; j < 4; ++j) {
                vA[j] = fast_exp2(vA[j] - mA); sA += vA[j];
                vB[j] = fast_exp2(vB[j] - mB); sB += vB[j];
            }
            sA += __shfl_xor_sync(0xffffffffu, sA, 1);
            sA += __shfl_xor_sync(0xffffffffu, sA, 2);
            sB += __shfl_xor_sync(0xffffffffu, sB, 1);
            sB += __shfl_xor_sync(0xffffffffu, sB, 2);

            // f in matching layout: r0:(cA, pk 2q/2q+1) r1:(cB,..) r2:(cA,+8) r3:(cB,+8)
            uint32_t fh[4], fl[4];
            LDSM_X4(fh, aggHiB + colb);
            LDSM_X4(fl, aggLoB + colb);

            float aggA, aggB;
            {
                float2 h, l, f0, f1;
                h = __bfloat1622float2(*(__nv_bfloat162*)&fh[0]);
                l = __bfloat1622float2(*(__nv_bfloat162*)&fl[0]);
                f0.x = h.x + l.x; f0.y = h.y + l.y;
                h = __bfloat1622float2(*(__nv_bfloat162*)&fh[2]);
                l = __bfloat1622float2(*(__nv_bfloat162*)&fl[2]);
                f1.x = h.x + l.x; f1.y = h.y + l.y;
                aggA = vA[0] * f0.x + vA[1] * f0.y + vA[2] * f1.x + vA[3] * f1.y;

                h = __bfloat1622float2(*(__nv_bfloat162*)&fh[1]);
                l = __bfloat1622float2(*(__nv_bfloat162*)&fl[1]);
                f0.x = h.x + l.x; f0.y = h.y + l.y;
                h = __bfloat1622float2(*(__nv_bfloat162*)&fh[3]);
                l = __bfloat1622float2(*(__nv_bfloat162*)&fl[3]);
                f1.x = h.x + l.x; f1.y = h.y + l.y;
                aggB = vB[0] * f0.x + vB[1] * f0.y + vB[2] * f1.x + vB[3] * f1.y;
            }
            aggA += __shfl_xor_sync(0xffffffffu, aggA, 1);
            aggA += __shfl_xor_sync(0xffffffffu, aggA, 2);
            aggB += __shfl_xor_sync(0xffffffffu, aggB, 1);
            aggB += __shfl_xor_sync(0xffffffffu, aggB, 2);

            if (qid == 0) {
                sAgg[pt * CMID + 16 * warp + gid]     = aggA / sA;
                sAgg[pt * CMID + 16 * warp + gid + 8] = aggB / sB;
            }
        }
        __syncthreads();

        // ================= phase 3: out-GEMM + store ======================
        {
            const float* aggw = sAgg + warp * CMID;   // warp -> point warp
            float4 oc = *(const float4*)(sbglob + 4 * lane);
#pragma unroll 1
            for (int c = 0; c < CMID; ++c) {
                const float av = aggw[c];
                const float4 w = *(const float4*)(sWglob + c * CMID + 4 * lane);
                oc.x = fmaf(av, w.x, oc.x);
                oc.y = fmaf(av, w.y, oc.y);
                oc.z = fmaf(av, w.z, oc.z);
                oc.w = fmaf(av, w.w, oc.w);
            }
            oc.x = fmaxf(oc.x, 0.0f);
            oc.y = fmaxf(oc.y, 0.0f);
            oc.z = fmaxf(oc.z, 0.0f);
            oc.w = fmaxf(oc.w, 0.0f);
            *(float4*)(sOut + warp * CMID + 4 * lane) = oc;
        }
        __syncthreads();
        {
            const int o  = tid >> 1;
            const int nn = (tid & 1) * 4;
            const int bb = p0 >> 14;
            const int n0 = p0 & (NPTS - 1);
            float4 v;
            v.x = sOut[(nn + 0) * CMID + o];
            v.y = sOut[(nn + 1) * CMID + o];
            v.z = sOut[(nn + 2) * CMID + o];
            v.w = sOut[(nn + 3) * CMID + o];
            *(float4*)(out + ((size_t)(bb * COUT + o)) * NPTS + n0 + nn) = v;
        }
        __syncthreads();
    }
}

// ---------------------------------------------------------------------------
extern "C" void kernel_launch(void* const* d_in, const int* in_sizes, int n_in,
                              void* d_out, int out_size) {
    const float* x     = (const float*)d_in[0];
    const float* pos   = (const float*)d_in[1];
    const int*   nidx  = (const int*)  d_in[2];
    const float* Wrel  = (const float*)d_in[3];
    const float* brel  = (const float*)d_in[4];
    const float* Watt  = (const float*)d_in[5];
    const float* Wglob = (const float*)d_in[6];
    const float* bglob = (const float*)d_in[7];
    float*       out   = (float*)d_out;

    transpose_x_kernel<<<dim3(NPTS / 32, CIN / 32, BATCH), dim3(32, 8)>>>(x);

    cudaFuncSetAttribute(randlanet_mma_kernel,
                         cudaFuncAttributeMaxDynamicSharedMemorySize, SMEM_BYTES);
    randlanet_mma_kernel<<<148, 256, SMEM_BYTES>>>(pos, nidx, Wrel, brel,
                                                   Watt, Wglob, bglob, out);
}

// round 8
// speedup vs baseline: 1.7970x; 1.2852x over previous
#include <cuda_runtime.h>
#include <cuda_bf16.h>
#include <cstdint>

// Problem constants
#define BATCH 4
#define NPTS  16384
#define KNN   16
#define CIN   64
#define DREL  64
#define CMID  128
#define COUT  128
#define GROUPS ((BATCH * NPTS) / 8)   // 8192 groups of 8 points
#define LOG2E 1.4426950408889634f
#define NTHREADS 512

// ---------------------------------------------------------------------------
// SMEM layout (bytes)
//   Fhi : [128 c rows][128 pk cols] bf16, row stride 272B (17x16B stride =>
//         ldmatrix row addresses hit distinct 16B banks, no swizzle needed)
//   Flo : same
//   Wglob fp32 [128][128]
//   Wrel fp32 [10][64], brel[64], bglob[128]
//   sAgg [8 pts][128], sOut [8 pts][128]
// ---------------------------------------------------------------------------
#define F_ROWSTRIDE 272
#define F_TILE      (128 * F_ROWSTRIDE + 64)     // 34880
#define OFF_FHI     0
#define OFF_FLO     (OFF_FHI + F_TILE)
#define OFF_WGLOB   (OFF_FLO + F_TILE)           // 69760
#define OFF_WREL    (OFF_WGLOB + 65536)
#define OFF_BREL    (OFF_WREL + 2560)
#define OFF_BGLOB   (OFF_BREL + 256)
#define OFF_AGG     (OFF_BGLOB + 512)
#define OFF_SOUT    (OFF_AGG + 4096)
#define SMEM_BYTES  (OFF_SOUT + 4096)            // 146816

// Scratch: transposed features xt[b][n][c]  (16 MB)
__device__ float g_xt[BATCH * NPTS * CIN];

// ---------------------------------------------------------------------------
static __device__ __forceinline__ uint32_t smem_u32(const void* p) {
    uint32_t a;
    asm("{ .reg .u64 t; cvta.to.shared.u64 t, %1; cvt.u32.u64 %0, t; }" : "=r"(a) : "l"(p));
    return a;
}

static __device__ __forceinline__ uint32_t frow(int c) {
    return (uint32_t)(c * F_ROWSTRIDE);
}

static __device__ __forceinline__ uint32_t pack_bf16x2(float v0, float v1) {
    __nv_bfloat162 h = __floats2bfloat162_rn(v0, v1);   // .x=v0 (low 16b)
    return *(uint32_t*)&h;
}

// fast 2^y : magic-rounding + degree-5 poly, FMA/ALU pipes only (no MUFU)
static __device__ __forceinline__ float fast_exp2(float y) {
    y = fmaxf(y, -80.0f);
    const float t = y + 12582912.0f;                    // 1.5 * 2^23
    const int   i = __float_as_int(t);
    const float f = y - (t - 12582912.0f);              // [-0.5, 0.5]
    float p = 0.00133335581f;
    p = fmaf(p, f, 0.00961812911f);
    p = fmaf(p, f, 0.05550410866f);
    p = fmaf(p, f, 0.24022650696f);
    p = fmaf(p, f, 0.69314718056f);
    p = fmaf(p, f, 1.0f);
    return __int_as_float(__float_as_int(p) + (i << 23));
}

#define MMA_BF16(D, A, B0, B1)                                                  \
    asm volatile("mma.sync.aligned.m16n8k16.row.col.f32.bf16.bf16.f32 "         \
                 "{%0,%1,%2,%3}, {%4,%5,%6,%7}, {%8,%9}, {%0,%1,%2,%3};"        \
                 : "+f"((D)[0]), "+f"((D)[1]), "+f"((D)[2]), "+f"((D)[3])       \
                 : "r"((A)[0]), "r"((A)[1]), "r"((A)[2]), "r"((A)[3]),          \
                   "r"(B0), "r"(B1))

#define LDSM_X2_T(R0, R1, ADDR)                                                 \
    asm volatile("ldmatrix.sync.aligned.m8n8.x2.trans.shared.b16 {%0,%1}, [%2];"\
                 : "=r"(R0), "=r"(R1) : "r"(ADDR))

#define LDSM_X4(R, ADDR)                                                        \
    asm volatile("ldmatrix.sync.aligned.m8n8.x4.shared.b16 {%0,%1,%2,%3}, [%4];"\
                 : "=r"((R)[0]), "=r"((R)[1]), "=r"((R)[2]), "=r"((R)[3])       \
                 : "r"(ADDR))

// ---------------------------------------------------------------------------
// Transpose x[B][64][N] -> g_xt[B][N][64]
// ---------------------------------------------------------------------------
__global__ void transpose_x_kernel(const float* __restrict__ x) {
    __shared__ float tile[32][33];
    const int b  = blockIdx.z;
    const int c0 = blockIdx.y * 32;
    const int n0 = blockIdx.x * 32;
    const int tx = threadIdx.x, ty = threadIdx.y;   // (32, 8)

    const float* xb = x + (size_t)b * CIN * NPTS;
#pragma unroll
    for (int i = 0; i < 4; ++i)
        tile[ty + 8 * i][tx] = xb[(size_t)(c0 + ty + 8 * i) * NPTS + n0 + tx];
    __syncthreads();
    float* xo = g_xt + ((size_t)b * NPTS + n0) * CIN;
#pragma unroll
    for (int i = 0; i < 4; ++i)
        xo[(size_t)(ty + 8 * i) * CIN + c0 + tx] = tile[tx][ty + 8 * i];
}

// ---------------------------------------------------------------------------
// Fused kernel. 148 persistent CTAs x 512 threads (16 warps).
//   phase 1: warp pair per point — warp 2p+h builds k-half h of point p
//   phase 2: warp w: o-chunk (w&7) x points (w>>3)*4..+3 — 3-MMA bf16 hi/lo
//            scores, lane-local+shfl softmax (FMA-poly exp2), agg -> sAgg
//   phase 3: warp pair per point splits 128 output channels (fp32 SIMT GEMM)
// ---------------------------------------------------------------------------
__global__ __launch_bounds__(NTHREADS, 1)
void randlanet_mma_kernel(const float* __restrict__ pos,
                          const int*   __restrict__ nidx,
                          const float* __restrict__ Wrel,
                          const float* __restrict__ brel,
                          const float* __restrict__ Watt,
                          const float* __restrict__ Wglob,
                          const float* __restrict__ bglob,
                          float*       __restrict__ out) {
    extern __shared__ char smem[];
    char*  sFhi   = smem + OFF_FHI;
    char*  sFlo   = smem + OFF_FLO;
    float* sWglob = (float*)(smem + OFF_WGLOB);
    float* sWrel  = (float*)(smem + OFF_WREL);
    float* sbrel  = (float*)(smem + OFF_BREL);
    float* sbglob = (float*)(smem + OFF_BGLOB);
    float* sAgg   = (float*)(smem + OFF_AGG);
    float* sOut   = (float*)(smem + OFF_SOUT);

    const uint32_t uFhi = smem_u32(sFhi);
    const uint32_t uFlo = smem_u32(sFlo);

    const int tid  = threadIdx.x;
    const int warp = tid >> 5;
    const int lane = tid & 31;
    const int gid  = lane >> 2;     // 0..7
    const int qid  = lane & 3;      // 0..3

    // phase-role indices
    const int pt1   = warp >> 1;    // phase 1: point
    const int kh    = warp & 1;     // phase 1: k-half (k = kh*8 .. kh*8+7)
    const int oc    = warp & 7;     // phase 2: o-chunk
    const int pbase = (warp >> 3) * 4;  // phase 2: first point
    const int pt3   = warp & 7;     // phase 3: point
    const int oh    = warp >> 3;    // phase 3: o-half

    // ---- cooperative load of fp32 weights ----
    for (int i = tid; i < CMID * CMID; i += NTHREADS) sWglob[i] = Wglob[i];
    for (int i = tid; i < 10 * DREL;   i += NTHREADS) sWrel[i]  = Wrel[i];
    if (tid < DREL) sbrel[tid]  = brel[tid];
    if (tid < COUT) sbglob[tid] = bglob[tid];

    // ---- W_att A-fragments for o-chunk oc, scaled by log2e, bf16 hi/lo ----
    uint32_t Ahi[8][4], Alo[8][4];
#pragma unroll
    for (int cc = 0; cc < 8; ++cc) {
#pragma unroll
        for (int r = 0; r < 4; ++r) {
            const int o = 16 * oc + gid + (r & 1) * 8;
            const int c = 16 * cc + 2 * qid + (r >> 1) * 8;
            const float v0 = Watt[c * CMID + o] * LOG2E;
            const float v1 = Watt[(c + 1) * CMID + o] * LOG2E;
            const __nv_bfloat16 h0 = __float2bfloat16(v0);
            const __nv_bfloat16 h1 = __float2bfloat16(v1);
            Ahi[cc][r] = pack_bf16x2(__bfloat162float(h0), __bfloat162float(h1));
            Alo[cc][r] = pack_bf16x2(v0 - __bfloat162float(h0),
                                     v1 - __bfloat162float(h1));
        }
    }
    __syncthreads();

    // per-lane ldmatrix base addresses (phase 2 B operand)
    uint32_t rowHi[8], rowLo[8];
#pragma unroll
    for (int cc = 0; cc < 8; ++cc) {
        const uint32_t fo = frow(16 * cc + (lane & 15));
        rowHi[cc] = uFhi + fo;
        rowLo[cc] = uFlo + fo;
    }
    const uint32_t aggOff = frow(16 * oc + (lane & 15)) + ((lane & 16) ? 16u : 0u);
    const uint32_t aggHiB = uFhi + aggOff;
    const uint32_t aggLoB = uFlo + aggOff;

    for (int g = blockIdx.x; g < GROUPS; g += gridDim.x) {
        const int p0 = g * 8;

        // ================= phase 1: build k-half of f for point pt1 =======
        {
            const int p  = p0 + pt1;
            const int b  = p >> 14;            // NPTS = 16384
            const int n  = p & (NPTS - 1);
            const float* posB = pos + (size_t)b * NPTS * 3;
            const float cx = posB[n * 3 + 0];
            const float cy = posB[n * 3 + 1];
            const float cz = posB[n * 3 + 2];
            int myidx = 0;
            if (lane < 8) myidx = nidx[(size_t)p * KNN + kh * 8 + lane];

#pragma unroll 1
            for (int k2 = 0; k2 < 8; k2 += 2) {
                const int id0 = __shfl_sync(0xffffffffu, myidx, k2);
                const int id1 = __shfl_sync(0xffffffffu, myidx, k2 + 1);
                float v0[4], v1[4];   // channels: lane, lane+32, 64+lane, 96+lane
#pragma unroll
                for (int s = 0; s < 2; ++s) {
                    const int id = s ? id1 : id0;
                    const float nx = posB[id * 3 + 0];
                    const float ny = posB[id * 3 + 1];
                    const float nz = posB[id * 3 + 2];
                    const float rx = nx - cx, ry = ny - cy, rz = nz - cz;
                    const float d  = sqrtf(rx * rx + ry * ry + rz * rz);
                    const float enc[10] = {cx, cy, cz, nx, ny, nz, rx, ry, rz, d};
                    float r0 = sbrel[lane];
                    float r1 = sbrel[lane + 32];
#pragma unroll
                    for (int e = 0; e < 10; ++e) {
                        r0 = fmaf(enc[e], sWrel[e * DREL + lane],      r0);
                        r1 = fmaf(enc[e], sWrel[e * DREL + lane + 32], r1);
                    }
                    const float* xr = g_xt + ((size_t)b * NPTS + id) * CIN;
                    float* v = s ? v1 : v0;
                    v[0] = fmaxf(r0, 0.0f);
                    v[1] = fmaxf(r1, 0.0f);
                    v[2] = xr[lane];
                    v[3] = xr[lane + 32];
                }
                const uint32_t pkb = (uint32_t)(pt1 * KNN + kh * 8 + k2) * 2;
                const int crow[4] = {lane, lane + 32, 64 + lane, 96 + lane};
#pragma unroll
                for (int s = 0; s < 4; ++s) {
                    const uint32_t fo = frow(crow[s]) + pkb;
                    const __nv_bfloat16 h0 = __float2bfloat16(v0[s]);
                    const __nv_bfloat16 h1 = __float2bfloat16(v1[s]);
                    *(uint32_t*)(sFhi + fo) =
                        pack_bf16x2(__bfloat162float(h0), __bfloat162float(h1));
                    *(uint32_t*)(sFlo + fo) =
                        pack_bf16x2(v0[s] - __bfloat162float(h0),
                                    v1[s] - __bfloat162float(h1));
                }
            }
        }
        __syncthreads();

        // ================= phase 2: MMA scores + softmax + agg ============
#pragma unroll 1
        for (int pp = 0; pp < 4; ++pp) {
            const int pt = pbase + pp;
            const uint32_t colb = (uint32_t)pt * 32;
            float d0[4] = {0.f, 0.f, 0.f, 0.f};   // pk half 0
            float d1[4] = {0.f, 0.f, 0.f, 0.f};   // pk half 1
#pragma unroll
            for (int cc = 0; cc < 8; ++cc) {
                uint32_t bh0, bh1, bl0, bl1;
                LDSM_X2_T(bh0, bh1, rowHi[cc] + colb);
                LDSM_X2_T(bl0, bl1, rowLo[cc] + colb);
                MMA_BF16(d0, Ahi[cc], bh0, bh1);
                MMA_BF16(d0, Ahi[cc], bl0, bl1);
                MMA_BF16(d0, Alo[cc], bh0, bh1);
                LDSM_X2_T(bh0, bh1, rowHi[cc] + colb + 16);
                LDSM_X2_T(bl0, bl1, rowLo[cc] + colb + 16);
                MMA_BF16(d1, Ahi[cc], bh0, bh1);
                MMA_BF16(d1, Ahi[cc], bl0, bl1);
                MMA_BF16(d1, Alo[cc], bh0, bh1);
            }

            // rows: A -> channel 16*oc+gid, B -> +8.  log2-domain scores.
            float vA[4] = {d0[0], d0[1], d1[0], d1[1]};
            float vB[4] = {d0[2], d0[3], d1[2], d1[3]};

            float mA = fmaxf(fmaxf(vA[0], vA[1]), fmaxf(vA[2], vA[3]));
            float mB = fmaxf(fmaxf(vB[0], vB[1]), fmaxf(vB[2], vB[3]));
            mA = fmaxf(mA, __shfl_xor_sync(0xffffffffu, mA, 1));
            mA = fmaxf(mA, __shfl_xor_sync(0xffffffffu, mA, 2));
            mB = fmaxf(mB, __shfl_xor_sync(0xffffffffu, mB, 1));
            mB = fmaxf(mB, __shfl_xor_sync(0xffffffffu, mB, 2));

            float sA = 0.f, sB = 0.f;
#pragma unroll
            for (int j = 0; j < 4; ++j) {
                vA[j] = fast_exp2(vA[j] - mA); sA += vA[j];
                vB[j] = fast_exp2(vB[j] - mB); sB += vB[j];
            }
            sA += __shfl_xor_sync(0xffffffffu, sA, 1);
            sA += __shfl_xor_sync(0xffffffffu, sA, 2);
            sB += __shfl_xor_sync(0xffffffffu, sB, 1);
            sB += __shfl_xor_sync(0xffffffffu, sB, 2);

            uint32_t fh[4], fl[4];
            LDSM_X4(fh, aggHiB + colb);
            LDSM_X4(fl, aggLoB + colb);

            float aggA, aggB;
            {
                float2 h, l, f0, f1;
                h = __bfloat1622float2(*(__nv_bfloat162*)&fh[0]);
                l = __bfloat1622float2(*(__nv_bfloat162*)&fl[0]);
                f0.x = h.x + l.x; f0.y = h.y + l.y;
                h = __bfloat1622float2(*(__nv_bfloat162*)&fh[2]);
                l = __bfloat1622float2(*(__nv_bfloat162*)&fl[2]);
                f1.x = h.x + l.x; f1.y = h.y + l.y;
                aggA = vA[0] * f0.x + vA[1] * f0.y + vA[2] * f1.x + vA[3] * f1.y;

                h = __bfloat1622float2(*(__nv_bfloat162*)&fh[1]);
                l = __bfloat1622float2(*(__nv_bfloat162*)&fl[1]);
                f0.x = h.x + l.x; f0.y = h.y + l.y;
                h = __bfloat1622float2(*(__nv_bfloat162*)&fh[3]);
                l = __bfloat1622float2(*(__nv_bfloat162*)&fl[3]);
                f1.x = h.x + l.x; f1.y = h.y + l.y;
                aggB = vB[0] * f0.x + vB[1] * f0.y + vB[2] * f1.x + vB[3] * f1.y;
            }
            aggA += __shfl_xor_sync(0xffffffffu, aggA, 1);
            aggA += __shfl_xor_sync(0xffffffffu, aggA, 2);
            aggB += __shfl_xor_sync(0xffffffffu, aggB, 1);
            aggB += __shfl_xor_sync(0xffffffffu, aggB, 2);

            if (qid == 0) {
                sAgg[pt * CMID + 16 * oc + gid]     = aggA / sA;
                sAgg[pt * CMID + 16 * oc + gid + 8] = aggB / sB;
            }
        }
        __syncthreads();

        // ================= phase 3: out-GEMM (warp pair per point) ========
        {
            const float* aggw = sAgg + pt3 * CMID;
            const int o0 = 64 * oh + 2 * lane;
            float2 oc2 = *(const float2*)(sbglob + o0);
#pragma unroll 1
            for (int c = 0; c < CMID; ++c) {
                const float av = aggw[c];
                const float2 w = *(const float2*)(sWglob + c * CMID + o0);
                oc2.x = fmaf(av, w.x, oc2.x);
                oc2.y = fmaf(av, w.y, oc2.y);
            }
            oc2.x = fmaxf(oc2.x, 0.0f);
            oc2.y = fmaxf(oc2.y, 0.0f);
            *(float2*)(sOut + pt3 * CMID + o0) = oc2;
        }
        __syncthreads();
        {
            const int o  = tid >> 2;
            const int nn = (tid & 3) * 2;
            const int bb = p0 >> 14;
            const int n0 = p0 & (NPTS - 1);
            float2 v;
            v.x = sOut[(nn + 0) * CMID + o];
            v.y = sOut[(nn + 1) * CMID + o];
            *(float2*)(out + ((size_t)(bb * COUT + o)) * NPTS + n0 + nn) = v;
        }
        __syncthreads();
    }
}

// ---------------------------------------------------------------------------
extern "C" void kernel_launch(void* const* d_in, const int* in_sizes, int n_in,
                              void* d_out, int out_size) {
    const float* x     = (const float*)d_in[0];
    const float* pos   = (const float*)d_in[1];
    const int*   nidx  = (const int*)  d_in[2];
    const float* Wrel  = (const float*)d_in[3];
    const float* brel  = (const float*)d_in[4];
    const float* Watt  = (const float*)d_in[5];
    const float* Wglob = (const float*)d_in[6];
    const float* bglob = (const float*)d_in[7];
    float*       out   = (float*)d_out;

    transpose_x_kernel<<<dim3(NPTS / 32, CIN / 32, BATCH), dim3(32, 8)>>>(x);

    cudaFuncSetAttribute(randlanet_mma_kernel,
                         cudaFuncAttributeMaxDynamicSharedMemorySize, SMEM_BYTES);
    randlanet_mma_kernel<<<148, NTHREADS, SMEM_BYTES>>>(pos, nidx, Wrel, brel,
                                                        Watt, Wglob, bglob, out);
}

// round 9
// speedup vs baseline: 1.8242x; 1.0151x over previous
#include <cuda_runtime.h>
#include <cuda_bf16.h>
#include <cstdint>

// Problem constants
#define BATCH 4
#define NPTS  16384
#define KNN   16
#define CIN   64
#define DREL  64
#define CMID  128
#define COUT  128
#define GROUPS ((BATCH * NPTS) / 8)   // 8192 groups of 8 points
#define LOG2E 1.4426950408889634f
#define NTHREADS 512

// ---------------------------------------------------------------------------
// SMEM layout (bytes)
//   Fhi : [128 c rows][128 pk cols] bf16, row stride 272B (17x16B stride =>
//         ldmatrix row addresses hit distinct 16B banks, no swizzle needed)
//   Flo : same (at fixed offset F_TILE from Fhi)
//   Wglob fp32 [128][128]
//   Wrel fp32 [10][64], brel[64], bglob[128]
//   sAgg [2 parity][8 pts][128] fp32 (double buffered)
// ---------------------------------------------------------------------------
#define F_ROWSTRIDE 272
#define F_TILE      (128 * F_ROWSTRIDE + 64)     // 34880
#define OFF_FHI     0
#define OFF_FLO     (OFF_FHI + F_TILE)
#define OFF_WGLOB   (OFF_FLO + F_TILE)           // 69760
#define OFF_WREL    (OFF_WGLOB + 65536)
#define OFF_BREL    (OFF_WREL + 2560)
#define OFF_BGLOB   (OFF_BREL + 256)
#define OFF_AGG     (OFF_BGLOB + 512)
#define SMEM_BYTES  (OFF_AGG + 2 * 4096)         // 146816 - 4096 + ...

// Scratch: transposed features xt[b][n][c]  (16 MB)
__device__ float g_xt[BATCH * NPTS * CIN];

// ---------------------------------------------------------------------------
static __device__ __forceinline__ uint32_t smem_u32(const void* p) {
    uint32_t a;
    asm("{ .reg .u64 t; cvta.to.shared.u64 t, %1; cvt.u32.u64 %0, t; }" : "=r"(a) : "l"(p));
    return a;
}

static __device__ __forceinline__ uint32_t frow(int c) {
    return (uint32_t)(c * F_ROWSTRIDE);
}

static __device__ __forceinline__ uint32_t pack_bf16x2(float v0, float v1) {
    __nv_bfloat162 h = __floats2bfloat162_rn(v0, v1);   // .x=v0 (low 16b)
    return *(uint32_t*)&h;
}

// fast 2^y : magic-rounding + degree-5 poly, FMA/ALU pipes only (no MUFU)
static __device__ __forceinline__ float fast_exp2(float y) {
    y = fmaxf(y, -80.0f);
    const float t = y + 12582912.0f;                    // 1.5 * 2^23
    const int   i = __float_as_int(t);
    const float f = y - (t - 12582912.0f);              // [-0.5, 0.5]
    float p = 0.00133335581f;
    p = fmaf(p, f, 0.00961812911f);
    p = fmaf(p, f, 0.05550410866f);
    p = fmaf(p, f, 0.24022650696f);
    p = fmaf(p, f, 0.69314718056f);
    p = fmaf(p, f, 1.0f);
    return __int_as_float(__float_as_int(p) + (i << 23));
}

#define MMA_BF16(D, A, B0, B1)                                                  \
    asm volatile("mma.sync.aligned.m16n8k16.row.col.f32.bf16.bf16.f32 "         \
                 "{%0,%1,%2,%3}, {%4,%5,%6,%7}, {%8,%9}, {%0,%1,%2,%3};"        \
                 : "+f"((D)[0]), "+f"((D)[1]), "+f"((D)[2]), "+f"((D)[3])       \
                 : "r"((A)[0]), "r"((A)[1]), "r"((A)[2]), "r"((A)[3]),          \
                   "r"(B0), "r"(B1))

#define LDSM_X2_T(R0, R1, ADDR)                                                 \
    asm volatile("ldmatrix.sync.aligned.m8n8.x2.trans.shared.b16 {%0,%1}, [%2];"\
                 : "=r"(R0), "=r"(R1) : "r"(ADDR))

#define LDSM_X4(R, ADDR)                                                        \
    asm volatile("ldmatrix.sync.aligned.m8n8.x4.shared.b16 {%0,%1,%2,%3}, [%4];"\
                 : "=r"((R)[0]), "=r"((R)[1]), "=r"((R)[2]), "=r"((R)[3])       \
                 : "r"(ADDR))

// ---------------------------------------------------------------------------
// Transpose x[B][64][N] -> g_xt[B][N][64]
// ---------------------------------------------------------------------------
__global__ void transpose_x_kernel(const float* __restrict__ x) {
    __shared__ float tile[32][33];
    const int b  = blockIdx.z;
    const int c0 = blockIdx.y * 32;
    const int n0 = blockIdx.x * 32;
    const int tx = threadIdx.x, ty = threadIdx.y;   // (32, 8)

    const float* xb = x + (size_t)b * CIN * NPTS;
#pragma unroll
    for (int i = 0; i < 4; ++i)
        tile[ty + 8 * i][tx] = xb[(size_t)(c0 + ty + 8 * i) * NPTS + n0 + tx];
    __syncthreads();
    float* xo = g_xt + ((size_t)b * NPTS + n0) * CIN;
#pragma unroll
    for (int i = 0; i < 4; ++i)
        xo[(size_t)(ty + 8 * i) * CIN + c0 + tx] = tile[tx][ty + 8 * i];
}

// ---------------------------------------------------------------------------
// Fused kernel. 148 persistent CTAs x 512 threads (16 warps).
//   phase 1: warp pair per point — warp 2p+h builds k-half h of point p
//   phase 2: warp w: o-chunk (w&7) x points (w>>3)*4..+3 — 3-MMA bf16 hi/lo
//            scores via 4 independent accumulator chains; lane-local+shfl
//            softmax (FMA-poly exp2); agg -> sAgg[parity]
//   phase 3: warp w owns o = 8w..8w+7 for ALL 8 points; reads Wglob once,
//            stores straight to global (full 32B sectors), no staging
// ---------------------------------------------------------------------------
__global__ __launch_bounds__(NTHREADS, 1)
void randlanet_mma_kernel(const float* __restrict__ pos,
                          const int*   __restrict__ nidx,
                          const float* __restrict__ Wrel,
                          const float* __restrict__ brel,
                          const float* __restrict__ Watt,
                          const float* __restrict__ Wglob,
                          const float* __restrict__ bglob,
                          float*       __restrict__ out) {
    extern __shared__ char smem[];
    char*  sFhi   = smem + OFF_FHI;
    char*  sFlo   = smem + OFF_FLO;
    float* sWglob = (float*)(smem + OFF_WGLOB);
    float* sWrel  = (float*)(smem + OFF_WREL);
    float* sbrel  = (float*)(smem + OFF_BREL);
    float* sbglob = (float*)(smem + OFF_BGLOB);
    float* sAgg   = (float*)(smem + OFF_AGG);    // [2][8][128]

    const uint32_t uFhi = smem_u32(sFhi);

    const int tid  = threadIdx.x;
    const int warp = tid >> 5;
    const int lane = tid & 31;
    const int gid  = lane >> 2;     // 0..7
    const int qid  = lane & 3;      // 0..3

    // phase-role indices
    const int pt1   = warp >> 1;        // phase 1: point
    const int kh    = warp & 1;         // phase 1: k-half
    const int oc    = warp & 7;         // phase 2: o-chunk
    const int pbase = (warp >> 3) * 4;  // phase 2: first point
    const int pt3   = lane >> 2;        // phase 3: point (0..7)
    const int o3    = warp * 8 + (lane & 3) * 2;   // phase 3: o pair

    // ---- cooperative load of fp32 weights ----
    for (int i = tid; i < CMID * CMID; i += NTHREADS) sWglob[i] = Wglob[i];
    for (int i = tid; i < 10 * DREL;   i += NTHREADS) sWrel[i]  = Wrel[i];
    if (tid < DREL) sbrel[tid]  = brel[tid];
    if (tid < COUT) sbglob[tid] = bglob[tid];

    // ---- W_att A-fragments for o-chunk oc, scaled by log2e, bf16 hi/lo ----
    uint32_t Ahi[8][4], Alo[8][4];
#pragma unroll
    for (int cc = 0; cc < 8; ++cc) {
#pragma unroll
        for (int r = 0; r < 4; ++r) {
            const int o = 16 * oc + gid + (r & 1) * 8;
            const int c = 16 * cc + 2 * qid + (r >> 1) * 8;
            const float v0 = Watt[c * CMID + o] * LOG2E;
            const float v1 = Watt[(c + 1) * CMID + o] * LOG2E;
            const __nv_bfloat16 h0 = __float2bfloat16(v0);
            const __nv_bfloat16 h1 = __float2bfloat16(v1);
            Ahi[cc][r] = pack_bf16x2(__bfloat162float(h0), __bfloat162float(h1));
            Alo[cc][r] = pack_bf16x2(v0 - __bfloat162float(h0),
                                     v1 - __bfloat162float(h1));
        }
    }
    __syncthreads();

    // per-lane ldmatrix base addresses (phase 2); lo tile = hi + F_TILE
    uint32_t rowHi[8];
#pragma unroll
    for (int cc = 0; cc < 8; ++cc)
        rowHi[cc] = uFhi + frow(16 * cc + (lane & 15));
    const uint32_t aggHiB = uFhi + frow(16 * oc + (lane & 15))
                          + ((lane & 16) ? 16u : 0u);

    for (int g = blockIdx.x; g < GROUPS; g += gridDim.x) {
        const int p0  = g * 8;
        const int par = (g / gridDim.x) & 1;
        float* aggBuf = sAgg + par * 8 * CMID;

        // ================= phase 1: build k-half of f for point pt1 =======
        {
            const int p  = p0 + pt1;
            const int b  = p >> 14;            // NPTS = 16384
            const int n  = p & (NPTS - 1);
            const float* posB = pos + (size_t)b * NPTS * 3;
            const float cx = posB[n * 3 + 0];
            const float cy = posB[n * 3 + 1];
            const float cz = posB[n * 3 + 2];
            int myidx = 0;
            if (lane < 8) myidx = nidx[(size_t)p * KNN + kh * 8 + lane];

#pragma unroll 1
            for (int k2 = 0; k2 < 8; k2 += 2) {
                const int id0 = __shfl_sync(0xffffffffu, myidx, k2);
                const int id1 = __shfl_sync(0xffffffffu, myidx, k2 + 1);
                float v0[4], v1[4];   // channels: lane, lane+32, 64+lane, 96+lane
#pragma unroll
                for (int s = 0; s < 2; ++s) {
                    const int id = s ? id1 : id0;
                    const float nx = posB[id * 3 + 0];
                    const float ny = posB[id * 3 + 1];
                    const float nz = posB[id * 3 + 2];
                    const float rx = nx - cx, ry = ny - cy, rz = nz - cz;
                    const float d  = sqrtf(rx * rx + ry * ry + rz * rz);
                    const float enc[10] = {cx, cy, cz, nx, ny, nz, rx, ry, rz, d};
                    float r0 = sbrel[lane];
                    float r1 = sbrel[lane + 32];
#pragma unroll
                    for (int e = 0; e < 10; ++e) {
                        r0 = fmaf(enc[e], sWrel[e * DREL + lane],      r0);
                        r1 = fmaf(enc[e], sWrel[e * DREL + lane + 32], r1);
                    }
                    const float* xr = g_xt + ((size_t)b * NPTS + id) * CIN;
                    float* v = s ? v1 : v0;
                    v[0] = fmaxf(r0, 0.0f);
                    v[1] = fmaxf(r1, 0.0f);
                    v[2] = xr[lane];
                    v[3] = xr[lane + 32];
                }
                const uint32_t pkb = (uint32_t)(pt1 * KNN + kh * 8 + k2) * 2;
                const int crow[4] = {lane, lane + 32, 64 + lane, 96 + lane};
#pragma unroll
                for (int s = 0; s < 4; ++s) {
                    const uint32_t fo = frow(crow[s]) + pkb;
                    const __nv_bfloat16 h0 = __float2bfloat16(v0[s]);
                    const __nv_bfloat16 h1 = __float2bfloat16(v1[s]);
                    *(uint32_t*)(sFhi + fo) =
                        pack_bf16x2(__bfloat162float(h0), __bfloat162float(h1));
                    *(uint32_t*)(sFlo + fo) =
                        pack_bf16x2(v0[s] - __bfloat162float(h0),
                                    v1[s] - __bfloat162float(h1));
                }
            }
        }
        __syncthreads();

        // ================= phase 2: MMA scores + softmax + agg ============
#pragma unroll 1
        for (int pp = 0; pp < 4; ++pp) {
            const int pt = pbase + pp;
            const uint32_t colb = (uint32_t)pt * 32;
            // 4 independent accumulator chains (a: hi*hi, b: lo corrections)
            float d0a[4] = {0.f, 0.f, 0.f, 0.f};
            float d0b[4] = {0.f, 0.f, 0.f, 0.f};
            float d1a[4] = {0.f, 0.f, 0.f, 0.f};
            float d1b[4] = {0.f, 0.f, 0.f, 0.f};
#pragma unroll
            for (int cc = 0; cc < 8; ++cc) {
                uint32_t h00, h01, l00, l01, h10, h11, l10, l11;
                const uint32_t aH = rowHi[cc] + colb;
                LDSM_X2_T(h00, h01, aH);
                LDSM_X2_T(l00, l01, aH + F_TILE);
                LDSM_X2_T(h10, h11, aH + 16);
                LDSM_X2_T(l10, l11, aH + F_TILE + 16);
                MMA_BF16(d0a, Ahi[cc], h00, h01);
                MMA_BF16(d1a, Ahi[cc], h10, h11);
                MMA_BF16(d0b, Ahi[cc], l00, l01);
                MMA_BF16(d1b, Ahi[cc], l10, l11);
                MMA_BF16(d0b, Alo[cc], h00, h01);
                MMA_BF16(d1b, Alo[cc], h10, h11);
            }

            // rows: A -> channel 16*oc+gid, B -> +8.  log2-domain scores.
            float vA[4] = {d0a[0] + d0b[0], d0a[1] + d0b[1],
                           d1a[0] + d1b[0], d1a[1] + d1b[1]};
            float vB[4] = {d0a[2] + d0b[2], d0a[3] + d0b[3],
                           d1a[2] + d1b[2], d1a[3] + d1b[3]};

            float mA = fmaxf(fmaxf(vA[0], vA[1]), fmaxf(vA[2], vA[3]));
            float mB = fmaxf(fmaxf(vB[0], vB[1]), fmaxf(vB[2], vB[3]));
            mA = fmaxf(mA, __shfl_xor_sync(0xffffffffu, mA, 1));
            mA = fmaxf(mA, __shfl_xor_sync(0xffffffffu, mA, 2));
            mB = fmaxf(mB, __shfl_xor_sync(0xffffffffu, mB, 1));
            mB = fmaxf(mB, __shfl_xor_sync(0xffffffffu, mB, 2));

            float sA = 0.f, sB = 0.f;
#pragma unroll
            for (int j = 0; j < 4; ++j) {
                vA[j] = fast_exp2(vA[j] - mA); sA += vA[j];
                vB[j] = fast_exp2(vB[j] - mB); sB += vB[j];
            }
            sA += __shfl_xor_sync(0xffffffffu, sA, 1);
            sA += __shfl_xor_sync(0xffffffffu, sA, 2);
            sB += __shfl_xor_sync(0xffffffffu, sB, 1);
            sB += __shfl_xor_sync(0xffffffffu, sB, 2);

            uint32_t fh[4], fl[4];
            LDSM_X4(fh, aggHiB + colb);
            LDSM_X4(fl, aggHiB + F_TILE + colb);

            float aggA, aggB;
            {
                float2 h, l, f0, f1;
                h = __bfloat1622float2(*(__nv_bfloat162*)&fh[0]);
                l = __bfloat1622float2(*(__nv_bfloat162*)&fl[0]);
                f0.x = h.x + l.x; f0.y = h.y + l.y;
                h = __bfloat1622float2(*(__nv_bfloat162*)&fh[2]);
                l = __bfloat1622float2(*(__nv_bfloat162*)&fl[2]);
                f1.x = h.x + l.x; f1.y = h.y + l.y;
                aggA = vA[0] * f0.x + vA[1] * f0.y + vA[2] * f1.x + vA[3] * f1.y;

                h = __bfloat1622float2(*(__nv_bfloat162*)&fh[1]);
                l = __bfloat1622float2(*(__nv_bfloat162*)&fl[1]);
                f0.x = h.x + l.x; f0.y = h.y + l.y;
                h = __bfloat1622float2(*(__nv_bfloat162*)&fh[3]);
                l = __bfloat1622float2(*(__nv_bfloat162*)&fl[3]);
                f1.x = h.x + l.x; f1.y = h.y + l.y;
                aggB = vB[0] * f0.x + vB[1] * f0.y + vB[2] * f1.x + vB[3] * f1.y;
            }
            aggA += __shfl_xor_sync(0xffffffffu, aggA, 1);
            aggA += __shfl_xor_sync(0xffffffffu, aggA, 2);
            aggB += __shfl_xor_sync(0xffffffffu, aggB, 1);
            aggB += __shfl_xor_sync(0xffffffffu, aggB, 2);

            if (qid == 0) {
                aggBuf[pt * CMID + 16 * oc + gid]     = aggA / sA;
                aggBuf[pt * CMID + 16 * oc + gid + 8] = aggB / sB;
            }
        }
        __syncthreads();

        // ================= phase 3: out-GEMM, direct store ================
        // warp owns o = 8*warp..+7, all 8 points; lane = (pt3, o-pair o3)
        {
            const float* aggp = aggBuf + pt3 * CMID;
            float2 acc = *(const float2*)(sbglob + o3);
#pragma unroll 4
            for (int c = 0; c < CMID; ++c) {
                const float av = aggp[c];
                const float2 w = *(const float2*)(sWglob + c * CMID + o3);
                acc.x = fmaf(av, w.x, acc.x);
                acc.y = fmaf(av, w.y, acc.y);
            }
            acc.x = fmaxf(acc.x, 0.0f);
            acc.y = fmaxf(acc.y, 0.0f);
            const int bb = p0 >> 14;
            const int n0 = p0 & (NPTS - 1);
            float* ob = out + (size_t)bb * COUT * NPTS + n0 + pt3;
            ob[(size_t)o3 * NPTS]       = acc.x;
            ob[(size_t)(o3 + 1) * NPTS] = acc.y;
        }
        // no barrier: next phase 1 touches F only; sAgg is double-buffered
    }
}

// ---------------------------------------------------------------------------
extern "C" void kernel_launch(void* const* d_in, const int* in_sizes, int n_in,
                              void* d_out, int out_size) {
    const float* x     = (const float*)d_in[0];
    const float* pos   = (const float*)d_in[1];
    const int*   nidx  = (const int*)  d_in[2];
    const float* Wrel  = (const float*)d_in[3];
    const float* brel  = (const float*)d_in[4];
    const float* Watt  = (const float*)d_in[5];
    const float* Wglob = (const float*)d_in[6];
    const float* bglob = (const float*)d_in[7];
    float*       out   = (float*)d_out;

    transpose_x_kernel<<<dim3(NPTS / 32, CIN / 32, BATCH), dim3(32, 8)>>>(x);

    cudaFuncSetAttribute(randlanet_mma_kernel,
                         cudaFuncAttributeMaxDynamicSharedMemorySize, SMEM_BYTES);
    randlanet_mma_kernel<<<148, NTHREADS, SMEM_BYTES>>>(pos, nidx, Wrel, brel,
                                                        Watt, Wglob, bglob, out);
}

// round 10
// speedup vs baseline: 2.0934x; 1.1476x over previous
#include <cuda_runtime.h>
#include <cuda_bf16.h>
#include <cstdint>

// Problem constants
#define BATCH 4
#define NPTS  16384
#define KNN   16
#define CIN   64
#define DREL  64
#define CMID  128
#define COUT  128
#define GROUPS ((BATCH * NPTS) / 8)   // 8192 groups of 8 points
#define LOG2E 1.4426950408889634f
#define NTHREADS 512

// ---------------------------------------------------------------------------
// SMEM layout (bytes)
//   Fhi : [128 c rows][128 pk cols] bf16, row stride 272B (17x16B stride =>
//         ldmatrix rows + STS.128 phases hit distinct banks, no swizzle)
//   Flo : same (fixed offset F_TILE from Fhi)
//   WglobT fp32 [128 o][c] row stride 130 floats (transposed, conflict-free)
//   Wrel fp32 [10][64], brel[64], bglob[128]
//   sAgg [2 parity][8 pts][128] fp32 (double buffered)
// ---------------------------------------------------------------------------
#define F_ROWSTRIDE 272
#define F_TILE      (128 * F_ROWSTRIDE + 64)     // 34880
#define WG_STRIDE   130
#define OFF_FHI     0
#define OFF_FLO     (OFF_FHI + F_TILE)
#define OFF_WGLOB   (OFF_FLO + F_TILE)           // 69760
#define OFF_WREL    (OFF_WGLOB + 128 * WG_STRIDE * 4)   // 136320
#define OFF_BREL    (OFF_WREL + 2560)
#define OFF_BGLOB   (OFF_BREL + 256)
#define OFF_AGG     (OFF_BGLOB + 512)
#define SMEM_BYTES  (OFF_AGG + 2 * 4096)         // 147840

// Scratch: transposed features xt[b][n][c]  (16 MB)
__device__ float g_xt[BATCH * NPTS * CIN];

// ---------------------------------------------------------------------------
static __device__ __forceinline__ uint32_t smem_u32(const void* p) {
    uint32_t a;
    asm("{ .reg .u64 t; cvta.to.shared.u64 t, %1; cvt.u32.u64 %0, t; }" : "=r"(a) : "l"(p));
    return a;
}

static __device__ __forceinline__ uint32_t frow(int c) {
    return (uint32_t)(c * F_ROWSTRIDE);
}

static __device__ __forceinline__ uint32_t pack_bf16x2(float v0, float v1) {
    __nv_bfloat162 h = __floats2bfloat162_rn(v0, v1);   // .x=v0 (low 16b)
    return *(uint32_t*)&h;
}

// split (v0,v1) into bf16 hi pair + bf16 lo-residual pair
static __device__ __forceinline__ void pack_pair(float v0, float v1,
                                                 uint32_t& h, uint32_t& l) {
    __nv_bfloat162 hh = __floats2bfloat162_rn(v0, v1);
    h = *(uint32_t*)&hh;
    l = pack_bf16x2(v0 - __bfloat162float(hh.x),
                    v1 - __bfloat162float(hh.y));
}

// fast 2^y : magic-rounding + degree-5 poly, FMA/ALU pipes only (no MUFU)
static __device__ __forceinline__ float fast_exp2(float y) {
    y = fmaxf(y, -80.0f);
    const float t = y + 12582912.0f;                    // 1.5 * 2^23
    const int   i = __float_as_int(t);
    const float f = y - (t - 12582912.0f);              // [-0.5, 0.5]
    float p = 0.00133335581f;
    p = fmaf(p, f, 0.00961812911f);
    p = fmaf(p, f, 0.05550410866f);
    p = fmaf(p, f, 0.24022650696f);
    p = fmaf(p, f, 0.69314718056f);
    p = fmaf(p, f, 1.0f);
    return __int_as_float(__float_as_int(p) + (i << 23));
}

#define MMA_BF16(D, A, B0, B1)                                                  \
    asm volatile("mma.sync.aligned.m16n8k16.row.col.f32.bf16.bf16.f32 "         \
                 "{%0,%1,%2,%3}, {%4,%5,%6,%7}, {%8,%9}, {%0,%1,%2,%3};"        \
                 : "+f"((D)[0]), "+f"((D)[1]), "+f"((D)[2]), "+f"((D)[3])       \
                 : "r"((A)[0]), "r"((A)[1]), "r"((A)[2]), "r"((A)[3]),          \
                   "r"(B0), "r"(B1))

#define LDSM_X4_T(R, ADDR)                                                      \
    asm volatile("ldmatrix.sync.aligned.m8n8.x4.trans.shared.b16 "              \
                 "{%0,%1,%2,%3}, [%4];"                                         \
                 : "=r"((R)[0]), "=r"((R)[1]), "=r"((R)[2]), "=r"((R)[3])       \
                 : "r"(ADDR))

#define LDSM_X4(R, ADDR)                                                        \
    asm volatile("ldmatrix.sync.aligned.m8n8.x4.shared.b16 {%0,%1,%2,%3}, [%4];"\
                 : "=r"((R)[0]), "=r"((R)[1]), "=r"((R)[2]), "=r"((R)[3])       \
                 : "r"(ADDR))

// ---------------------------------------------------------------------------
// Transpose x[B][64][N] -> g_xt[B][N][64]
// ---------------------------------------------------------------------------
__global__ void transpose_x_kernel(const float* __restrict__ x) {
    __shared__ float tile[32][33];
    const int b  = blockIdx.z;
    const int c0 = blockIdx.y * 32;
    const int n0 = blockIdx.x * 32;
    const int tx = threadIdx.x, ty = threadIdx.y;   // (32, 8)

    const float* xb = x + (size_t)b * CIN * NPTS;
#pragma unroll
    for (int i = 0; i < 4; ++i)
        tile[ty + 8 * i][tx] = xb[(size_t)(c0 + ty + 8 * i) * NPTS + n0 + tx];
    __syncthreads();
    float* xo = g_xt + ((size_t)b * NPTS + n0) * CIN;
#pragma unroll
    for (int i = 0; i < 4; ++i)
        xo[(size_t)(ty + 8 * i) * CIN + c0 + tx] = tile[tx][ty + 8 * i];
}

// ---------------------------------------------------------------------------
// Fused kernel. 148 persistent CTAs x 512 threads (16 warps).
//   phase 1: warp (2p+h) builds k-half h of point p: rows packed in registers
//            (8 bf16 = 16B per channel row), written via conflict-free STS.128
//   phase 2: warp w: o-chunk (w&7) x points (w>>3)*4..+3; B operands via
//            ldmatrix.x4.trans; 3-product bf16 hi/lo MMA on 4 indep chains;
//            shfl softmax (FMA exp2); agg -> sAgg[parity]
//   phase 3: lane owns channel o=8w+(lane&7), two points; WglobT rows
// ---------------------------------------------------------------------------
__global__ __launch_bounds__(NTHREADS, 1)
void randlanet_mma_kernel(const float* __restrict__ pos,
                          const int*   __restrict__ nidx,
                          const float* __restrict__ Wrel,
                          const float* __restrict__ brel,
                          const float* __restrict__ Watt,
                          const float* __restrict__ Wglob,
                          const float* __restrict__ bglob,
                          float*       __restrict__ out) {
    extern __shared__ char smem[];
    char*  sFhi    = smem + OFF_FHI;
    char*  sFlo    = smem + OFF_FLO;
    float* sWglobT = (float*)(smem + OFF_WGLOB);
    float* sWrel   = (float*)(smem + OFF_WREL);
    float* sbrel   = (float*)(smem + OFF_BREL);
    float* sbglob  = (float*)(smem + OFF_BGLOB);
    float* sAgg    = (float*)(smem + OFF_AGG);    // [2][8][128]

    const uint32_t uFhi = smem_u32(sFhi);

    const int tid  = threadIdx.x;
    const int warp = tid >> 5;
    const int lane = tid & 31;
    const int gid  = lane >> 2;     // 0..7
    const int qid  = lane & 3;      // 0..3

    // phase-role indices
    const int pt1   = warp >> 1;        // phase 1: point
    const int kh    = warp & 1;         // phase 1: k-half
    const int oc    = warp & 7;         // phase 2: o-chunk
    const int pbase = (warp >> 3) * 4;  // phase 2: first point
    const int o3    = warp * 8 + (lane & 7);   // phase 3: channel
    const int pA3   = lane >> 3;               // phase 3: point A (0..3)

    // ---- cooperative load of fp32 weights (WglobT transposed, padded) ----
    for (int i = tid; i < CMID * CMID; i += NTHREADS) {
        const int o = i >> 7, c = i & 127;
        sWglobT[o * WG_STRIDE + c] = Wglob[c * CMID + o];
    }
    for (int i = tid; i < 10 * DREL; i += NTHREADS) sWrel[i] = Wrel[i];
    if (tid < DREL) sbrel[tid]  = brel[tid];
    if (tid < COUT) sbglob[tid] = bglob[tid];

    // ---- W_att A-fragments for o-chunk oc, scaled by log2e, bf16 hi/lo ----
    uint32_t Ahi[8][4], Alo[8][4];
#pragma unroll
    for (int cc = 0; cc < 8; ++cc) {
#pragma unroll
        for (int r = 0; r < 4; ++r) {
            const int o = 16 * oc + gid + (r & 1) * 8;
            const int c = 16 * cc + 2 * qid + (r >> 1) * 8;
            const float v0 = Watt[c * CMID + o] * LOG2E;
            const float v1 = Watt[(c + 1) * CMID + o] * LOG2E;
            pack_pair(v0, v1, Ahi[cc][r], Alo[cc][r]);
        }
    }
    __syncthreads();

    // ldmatrix x4 base: lanes 0-15 -> (channel rows, col), 16-31 -> col+16
    uint32_t rowB[8];
#pragma unroll
    for (int cc = 0; cc < 8; ++cc)
        rowB[cc] = uFhi + frow(16 * cc + (lane & 15)) + ((lane & 16) ? 16u : 0u);
    const uint32_t aggHiB = uFhi + frow(16 * oc + (lane & 15))
                          + ((lane & 16) ? 16u : 0u);

    for (int g = blockIdx.x; g < GROUPS; g += gridDim.x) {
        const int p0  = g * 8;
        const int par = (g / gridDim.x) & 1;
        float* aggBuf = sAgg + par * 8 * CMID;
        const int bb = p0 >> 14;            // NPTS = 16384
        const int n0 = p0 & (NPTS - 1);

        // ================= phase 1: build k-half of f for point pt1 =======
        {
            const int p = p0 + pt1;
            const int n = (p & (NPTS - 1));
            const float* posB = pos + (size_t)bb * NPTS * 3;
            const float cx = posB[n * 3 + 0];
            const float cy = posB[n * 3 + 1];
            const float cz = posB[n * 3 + 2];
            int myidx = 0;
            if (lane < 8) myidx = nidx[(size_t)p * KNN + kh * 8 + lane];
            const uint32_t rowbase = (uint32_t)(pt1 * 32 + kh * 16);

            // ---- pass B: gathered features, channel rows 64+lane, 96+lane
            {
                uint32_t gh[8], gl[8];
#pragma unroll
                for (int k2 = 0; k2 < 8; k2 += 2) {
                    const int id0 = __shfl_sync(0xffffffffu, myidx, k2);
                    const int id1 = __shfl_sync(0xffffffffu, myidx, k2 + 1);
                    const float* x0 = g_xt + ((size_t)bb * NPTS + id0) * CIN;
                    const float* x1 = g_xt + ((size_t)bb * NPTS + id1) * CIN;
                    pack_pair(x0[lane],      x1[lane],      gh[k2 >> 1],       gl[k2 >> 1]);
                    pack_pair(x0[lane + 32], x1[lane + 32], gh[4 + (k2 >> 1)], gl[4 + (k2 >> 1)]);
                }
                const uint32_t r0 = frow(64 + lane) + rowbase;
                const uint32_t r1 = frow(96 + lane) + rowbase;
                *(uint4*)(sFhi + r0) = make_uint4(gh[0], gh[1], gh[2], gh[3]);
                *(uint4*)(sFlo + r0) = make_uint4(gl[0], gl[1], gl[2], gl[3]);
                *(uint4*)(sFhi + r1) = make_uint4(gh[4], gh[5], gh[6], gh[7]);
                *(uint4*)(sFlo + r1) = make_uint4(gl[4], gl[5], gl[6], gl[7]);
            }
            // ---- pass A: rel-MLP, channel rows lane, lane+32
            {
                uint32_t gh[8], gl[8];
#pragma unroll
                for (int k2 = 0; k2 < 8; k2 += 2) {
                    float ra[2], rb[2];
#pragma unroll
                    for (int s = 0; s < 2; ++s) {
                        const int id = __shfl_sync(0xffffffffu, myidx, k2 + s);
                        const float nx = posB[id * 3 + 0];
                        const float ny = posB[id * 3 + 1];
                        const float nz = posB[id * 3 + 2];
                        const float rx = nx - cx, ry = ny - cy, rz = nz - cz;
                        const float d  = sqrtf(rx * rx + ry * ry + rz * rz);
                        const float enc[10] = {cx, cy, cz, nx, ny, nz, rx, ry, rz, d};
                        float a0 = sbrel[lane];
                        float a1 = sbrel[lane + 32];
#pragma unroll
                        for (int e = 0; e < 10; ++e) {
                            a0 = fmaf(enc[e], sWrel[e * DREL + lane],      a0);
                            a1 = fmaf(enc[e], sWrel[e * DREL + lane + 32], a1);
                        }
                        ra[s] = fmaxf(a0, 0.0f);
                        rb[s] = fmaxf(a1, 0.0f);
                    }
                    pack_pair(ra[0], ra[1], gh[k2 >> 1],       gl[k2 >> 1]);
                    pack_pair(rb[0], rb[1], gh[4 + (k2 >> 1)], gl[4 + (k2 >> 1)]);
                }
                const uint32_t r0 = frow(lane) + rowbase;
                const uint32_t r1 = frow(lane + 32) + rowbase;
                *(uint4*)(sFhi + r0) = make_uint4(gh[0], gh[1], gh[2], gh[3]);
                *(uint4*)(sFlo + r0) = make_uint4(gl[0], gl[1], gl[2], gl[3]);
                *(uint4*)(sFhi + r1) = make_uint4(gh[4], gh[5], gh[6], gh[7]);
                *(uint4*)(sFlo + r1) = make_uint4(gl[4], gl[5], gl[6], gl[7]);
            }
        }
        __syncthreads();

        // ================= phase 2: MMA scores + softmax + agg ============
#pragma unroll 1
        for (int pp = 0; pp < 4; ++pp) {
            const int pt = pbase + pp;
            const uint32_t colb = (uint32_t)pt * 32;
            float d0a[4] = {0.f, 0.f, 0.f, 0.f};
            float d0b[4] = {0.f, 0.f, 0.f, 0.f};
            float d1a[4] = {0.f, 0.f, 0.f, 0.f};
            float d1b[4] = {0.f, 0.f, 0.f, 0.f};
#pragma unroll
            for (int cc = 0; cc < 8; ++cc) {
                uint32_t bh[4], bl[4];
                LDSM_X4_T(bh, rowB[cc] + colb);
                LDSM_X4_T(bl, rowB[cc] + colb + F_TILE);
                MMA_BF16(d0a, Ahi[cc], bh[0], bh[1]);
                MMA_BF16(d1a, Ahi[cc], bh[2], bh[3]);
                MMA_BF16(d0b, Ahi[cc], bl[0], bl[1]);
                MMA_BF16(d1b, Ahi[cc], bl[2], bl[3]);
                MMA_BF16(d0b, Alo[cc], bh[0], bh[1]);
                MMA_BF16(d1b, Alo[cc], bh[2], bh[3]);
            }

            float vA[4] = {d0a[0] + d0b[0], d0a[1] + d0b[1],
                           d1a[0] + d1b[0], d1a[1] + d1b[1]};
            float vB[4] = {d0a[2] + d0b[2], d0a[3] + d0b[3],
                           d1a[2] + d1b[2], d1a[3] + d1b[3]};

            float mA = fmaxf(fmaxf(vA[0], vA[1]), fmaxf(vA[2], vA[3]));
            float mB = fmaxf(fmaxf(vB[0], vB[1]), fmaxf(vB[2], vB[3]));
            mA = fmaxf(mA, __shfl_xor_sync(0xffffffffu, mA, 1));
            mA = fmaxf(mA, __shfl_xor_sync(0xffffffffu, mA, 2));
            mB = fmaxf(mB, __shfl_xor_sync(0xffffffffu, mB, 1));
            mB = fmaxf(mB, __shfl_xor_sync(0xffffffffu, mB, 2));

            float sA = 0.f, sB = 0.f;
#pragma unroll
            for (int j = 0; j < 4; ++j) {
                vA[j] = fast_exp2(vA[j] - mA); sA += vA[j];
                vB[j] = fast_exp2(vB[j] - mB); sB += vB[j];
            }
            sA += __shfl_xor_sync(0xffffffffu, sA, 1);
            sA += __shfl_xor_sync(0xffffffffu, sA, 2);
            sB += __shfl_xor_sync(0xffffffffu, sB, 1);
            sB += __shfl_xor_sync(0xffffffffu, sB, 2);

            uint32_t fh[4], fl[4];
            LDSM_X4(fh, aggHiB + colb);
            LDSM_X4(fl, aggHiB + F_TILE + colb);

            float aggA, aggB;
            {
                float2 h, l, f0, f1;
                h = __bfloat1622float2(*(__nv_bfloat162*)&fh[0]);
                l = __bfloat1622float2(*(__nv_bfloat162*)&fl[0]);
                f0.x = h.x + l.x; f0.y = h.y + l.y;
                h = __bfloat1622float2(*(__nv_bfloat162*)&fh[2]);
                l = __bfloat1622float2(*(__nv_bfloat162*)&fl[2]);
                f1.x = h.x + l.x; f1.y = h.y + l.y;
                aggA = vA[0] * f0.x + vA[1] * f0.y + vA[2] * f1.x + vA[3] * f1.y;

                h = __bfloat1622float2(*(__nv_bfloat162*)&fh[1]);
                l = __bfloat1622float2(*(__nv_bfloat162*)&fl[1]);
                f0.x = h.x + l.x; f0.y = h.y + l.y;
                h = __bfloat1622float2(*(__nv_bfloat162*)&fh[3]);
                l = __bfloat1622float2(*(__nv_bfloat162*)&fl[3]);
                f1.x = h.x + l.x; f1.y = h.y + l.y;
                aggB = vB[0] * f0.x + vB[1] * f0.y + vB[2] * f1.x + vB[3] * f1.y;
            }
            aggA += __shfl_xor_sync(0xffffffffu, aggA, 1);
            aggA += __shfl_xor_sync(0xffffffffu, aggA, 2);
            aggB += __shfl_xor_sync(0xffffffffu, aggB, 1);
            aggB += __shfl_xor_sync(0xffffffffu, aggB, 2);

            if (qid == 0) {
                aggBuf[pt * CMID + 16 * oc + gid]     = aggA / sA;
                aggBuf[pt * CMID + 16 * oc + gid + 8] = aggB / sB;
            }
        }
        __syncthreads();

        // ================= phase 3: out-GEMM, direct store ================
        // lane owns channel o3, points pA3 and pA3+4
        {
            const float* wrow = sWglobT + o3 * WG_STRIDE;
            const float* agA  = aggBuf + pA3 * CMID;
            const float* agB  = agA + 4 * CMID;
            float accA = sbglob[o3];
            float accB = accA;
#pragma unroll 8
            for (int c = 0; c < CMID; c += 2) {
                const float2 w2 = *(const float2*)(wrow + c);
                const float2 a1 = *(const float2*)(agA + c);
                const float2 a2 = *(const float2*)(agB + c);
                accA = fmaf(a1.x, w2.x, fmaf(a1.y, w2.y, accA));
                accB = fmaf(a2.x, w2.x, fmaf(a2.y, w2.y, accB));
            }
            accA = fmaxf(accA, 0.0f);
            accB = fmaxf(accB, 0.0f);
            float* ob = out + (size_t)bb * COUT * NPTS + (size_t)o3 * NPTS + n0;
            ob[pA3]     = accA;
            ob[pA3 + 4] = accB;
        }
        // no barrier: next phase 1 touches F only; sAgg is double-buffered
    }
}

// ---------------------------------------------------------------------------
extern "C" void kernel_launch(void* const* d_in, const int* in_sizes, int n_in,
                              void* d_out, int out_size) {
    const float* x     = (const float*)d_in[0];
    const float* pos   = (const float*)d_in[1];
    const int*   nidx  = (const int*)  d_in[2];
    const float* Wrel  = (const float*)d_in[3];
    const float* brel  = (const float*)d_in[4];
    const float* Watt  = (const float*)d_in[5];
    const float* Wglob = (const float*)d_in[6];
    const float* bglob = (const float*)d_in[7];
    float*       out   = (float*)d_out;

    transpose_x_kernel<<<dim3(NPTS / 32, CIN / 32, BATCH), dim3(32, 8)>>>(x);

    cudaFuncSetAttribute(randlanet_mma_kernel,
                         cudaFuncAttributeMaxDynamicSharedMemorySize, SMEM_BYTES);
    randlanet_mma_kernel<<<148, NTHREADS, SMEM_BYTES>>>(pos, nidx, Wrel, brel,
                                                        Watt, Wglob, bglob, out);
}

// round 11
// speedup vs baseline: 2.2456x; 1.0727x over previous
#include <cuda_runtime.h>
#include <cuda_bf16.h>
#include <cstdint>

// Problem constants
#define BATCH 4
#define NPTS  16384
#define KNN   16
#define CIN   64
#define DREL  64
#define CMID  128
#define COUT  128
#define GROUPS ((BATCH * NPTS) / 8)   // 8192 groups of 8 points
#define LOG2E 1.4426950408889634f
#define NTHREADS 512

// ---------------------------------------------------------------------------
// SMEM layout (bytes)
//   Fhi : [128 c rows][128 pk cols] bf16, row stride 272B (17x16B stride =>
//         ldmatrix rows + STS.128 phases hit distinct banks, no swizzle)
//   Flo : same (fixed offset F_TILE from Fhi)
//   WglobT fp32 [128 o][c] row stride 132 floats (16B-aligned, conflict-free)
//   Wrel fp32 [10][64], brel[64], bglob[128]
//   sAgg [2 parity][8 pts][132] fp32 (double buffered, 16B-aligned rows)
// ---------------------------------------------------------------------------
#define F_ROWSTRIDE 272
#define F_TILE      (128 * F_ROWSTRIDE + 64)     // 34880
#define WG_STRIDE   132
#define AGG_STRIDE  132
#define OFF_FHI     0
#define OFF_FLO     (OFF_FHI + F_TILE)
#define OFF_WGLOB   (OFF_FLO + F_TILE)                   // 69760
#define OFF_WREL    (OFF_WGLOB + 128 * WG_STRIDE * 4)    // 137344
#define OFF_BREL    (OFF_WREL + 2560)
#define OFF_BGLOB   (OFF_BREL + 256)
#define OFF_AGG     (OFF_BGLOB + 512)                    // 140672 (16B aligned)
#define SMEM_BYTES  (OFF_AGG + 2 * 8 * AGG_STRIDE * 4)   // 149120

// Scratch: packed bf16 hi/lo of transposed features: word = hi | (lo<<16)
__device__ uint32_t g_xtp[BATCH * NPTS * CIN];

// ---------------------------------------------------------------------------
static __device__ __forceinline__ uint32_t smem_u32(const void* p) {
    uint32_t a;
    asm("{ .reg .u64 t; cvta.to.shared.u64 t, %1; cvt.u32.u64 %0, t; }" : "=r"(a) : "l"(p));
    return a;
}

static __device__ __forceinline__ uint32_t frow(int c) {
    return (uint32_t)(c * F_ROWSTRIDE);
}

static __device__ __forceinline__ uint32_t pack_bf16x2(float v0, float v1) {
    __nv_bfloat162 h = __floats2bfloat162_rn(v0, v1);   // .x=v0 (low 16b)
    return *(uint32_t*)&h;
}

// split (v0,v1) into bf16 hi pair + bf16 lo-residual pair
static __device__ __forceinline__ void pack_pair(float v0, float v1,
                                                 uint32_t& h, uint32_t& l) {
    __nv_bfloat162 hh = __floats2bfloat162_rn(v0, v1);
    h = *(uint32_t*)&hh;
    l = pack_bf16x2(v0 - __bfloat162float(hh.x),
                    v1 - __bfloat162float(hh.y));
}

// fast 2^y : magic-rounding + degree-5 poly, FMA/ALU pipes only (no MUFU)
static __device__ __forceinline__ float fast_exp2(float y) {
    y = fmaxf(y, -80.0f);
    const float t = y + 12582912.0f;                    // 1.5 * 2^23
    const int   i = __float_as_int(t);
    const float f = y - (t - 12582912.0f);              // [-0.5, 0.5]
    float p = 0.00133335581f;
    p = fmaf(p, f, 0.00961812911f);
    p = fmaf(p, f, 0.05550410866f);
    p = fmaf(p, f, 0.24022650696f);
    p = fmaf(p, f, 0.69314718056f);
    p = fmaf(p, f, 1.0f);
    return __int_as_float(__float_as_int(p) + (i << 23));
}

#define MMA_BF16(D, A, B0, B1)                                                  \
    asm volatile("mma.sync.aligned.m16n8k16.row.col.f32.bf16.bf16.f32 "         \
                 "{%0,%1,%2,%3}, {%4,%5,%6,%7}, {%8,%9}, {%0,%1,%2,%3};"        \
                 : "+f"((D)[0]), "+f"((D)[1]), "+f"((D)[2]), "+f"((D)[3])       \
                 : "r"((A)[0]), "r"((A)[1]), "r"((A)[2]), "r"((A)[3]),          \
                   "r"(B0), "r"(B1))

#define LDSM_X4_T(R, ADDR)                                                      \
    asm volatile("ldmatrix.sync.aligned.m8n8.x4.trans.shared.b16 "              \
                 "{%0,%1,%2,%3}, [%4];"                                         \
                 : "=r"((R)[0]), "=r"((R)[1]), "=r"((R)[2]), "=r"((R)[3])       \
                 : "r"(ADDR))

#define LDSM_X4(R, ADDR)                                                        \
    asm volatile("ldmatrix.sync.aligned.m8n8.x4.shared.b16 {%0,%1,%2,%3}, [%4];"\
                 : "=r"((R)[0]), "=r"((R)[1]), "=r"((R)[2]), "=r"((R)[3])       \
                 : "r"(ADDR))

// ---------------------------------------------------------------------------
// Transpose + hi/lo split: x[B][64][N] -> g_xtp[B][N][64] (hi | lo<<16)
// ---------------------------------------------------------------------------
__global__ void transpose_x_kernel(const float* __restrict__ x) {
    __shared__ float tile[32][33];
    const int b  = blockIdx.z;
    const int c0 = blockIdx.y * 32;
    const int n0 = blockIdx.x * 32;
    const int tx = threadIdx.x, ty = threadIdx.y;   // (32, 8)

    const float* xb = x + (size_t)b * CIN * NPTS;
#pragma unroll
    for (int i = 0; i < 4; ++i)
        tile[ty + 8 * i][tx] = xb[(size_t)(c0 + ty + 8 * i) * NPTS + n0 + tx];
    __syncthreads();
    uint32_t* xo = g_xtp + ((size_t)b * NPTS + n0) * CIN;
#pragma unroll
    for (int i = 0; i < 4; ++i) {
        const float v = tile[tx][ty + 8 * i];
        const __nv_bfloat16 h = __float2bfloat16(v);
        const __nv_bfloat16 l = __float2bfloat16(v - __bfloat162float(h));
        const uint32_t w = (uint32_t)*(const uint16_t*)&h
                         | ((uint32_t)*(const uint16_t*)&l << 16);
        xo[(size_t)(ty + 8 * i) * CIN + c0 + tx] = w;
    }
}

// ---------------------------------------------------------------------------
// Fused kernel. 148 persistent CTAs x 512 threads (16 warps).
//   phase 1: warp (2p+h) builds k-half h of point p (register-packed rows,
//            conflict-free STS.128; x features come pre-split from g_xtp)
//   phase 2: warp w: o-chunk (w&7) x points (w>>3)*4..+3, unrolled 2 points
//            deep; 3-product bf16 hi/lo MMA; shfl softmax (FMA exp2)
//   phase 3: lane owns channel o=8w+(lane&7), 2 points; float4 LDS
// ---------------------------------------------------------------------------
__global__ __launch_bounds__(NTHREADS, 1)
void randlanet_mma_kernel(const float* __restrict__ pos,
                          const int*   __restrict__ nidx,
                          const float* __restrict__ Wrel,
                          const float* __restrict__ brel,
                          const float* __restrict__ Watt,
                          const float* __restrict__ Wglob,
                          const float* __restrict__ bglob,
                          float*       __restrict__ out) {
    extern __shared__ char smem[];
    char*  sFhi    = smem + OFF_FHI;
    char*  sFlo    = smem + OFF_FLO;
    float* sWglobT = (float*)(smem + OFF_WGLOB);
    float* sWrel   = (float*)(smem + OFF_WREL);
    float* sbrel   = (float*)(smem + OFF_BREL);
    float* sbglob  = (float*)(smem + OFF_BGLOB);
    float* sAgg    = (float*)(smem + OFF_AGG);    // [2][8][AGG_STRIDE]

    const uint32_t uFhi = smem_u32(sFhi);

    const int tid  = threadIdx.x;
    const int warp = tid >> 5;
    const int lane = tid & 31;
    const int gid  = lane >> 2;     // 0..7
    const int qid  = lane & 3;      // 0..3

    // phase-role indices
    const int pt1   = warp >> 1;        // phase 1: point
    const int kh    = warp & 1;         // phase 1: k-half
    const int oc    = warp & 7;         // phase 2: o-chunk
    const int pbase = (warp >> 3) * 4;  // phase 2: first point
    const int o3    = warp * 8 + (lane & 7);   // phase 3: channel
    const int pA3   = lane >> 3;               // phase 3: point A (0..3)

    // ---- cooperative load of fp32 weights (WglobT transposed, padded) ----
    for (int i = tid; i < CMID * CMID; i += NTHREADS) {
        const int o = i >> 7, c = i & 127;
        sWglobT[o * WG_STRIDE + c] = Wglob[c * CMID + o];
    }
    for (int i = tid; i < 10 * DREL; i += NTHREADS) sWrel[i] = Wrel[i];
    if (tid < DREL) sbrel[tid]  = brel[tid];
    if (tid < COUT) sbglob[tid] = bglob[tid];

    // ---- W_att A-fragments for o-chunk oc, scaled by log2e, bf16 hi/lo ----
    uint32_t Ahi[8][4], Alo[8][4];
#pragma unroll
    for (int cc = 0; cc < 8; ++cc) {
#pragma unroll
        for (int r = 0; r < 4; ++r) {
            const int o = 16 * oc + gid + (r & 1) * 8;
            const int c = 16 * cc + 2 * qid + (r >> 1) * 8;
            const float v0 = Watt[c * CMID + o] * LOG2E;
            const float v1 = Watt[(c + 1) * CMID + o] * LOG2E;
            pack_pair(v0, v1, Ahi[cc][r], Alo[cc][r]);
        }
    }
    __syncthreads();

    // ldmatrix x4 base: lanes 0-15 -> (channel rows, col), 16-31 -> col+16
    uint32_t rowB[8];
#pragma unroll
    for (int cc = 0; cc < 8; ++cc)
        rowB[cc] = uFhi + frow(16 * cc + (lane & 15)) + ((lane & 16) ? 16u : 0u);
    const uint32_t aggHiB = uFhi + frow(16 * oc + (lane & 15))
                          + ((lane & 16) ? 16u : 0u);

    for (int g = blockIdx.x; g < GROUPS; g += gridDim.x) {
        const int p0  = g * 8;
        const int par = (g / gridDim.x) & 1;
        float* aggBuf = sAgg + par * 8 * AGG_STRIDE;
        const int bb = p0 >> 14;            // NPTS = 16384
        const int n0 = p0 & (NPTS - 1);

        // ================= phase 1: build k-half of f for point pt1 =======
        {
            const int p = p0 + pt1;
            const int n = (p & (NPTS - 1));
            const float* posB = pos + (size_t)bb * NPTS * 3;
            const float cx = posB[n * 3 + 0];
            const float cy = posB[n * 3 + 1];
            const float cz = posB[n * 3 + 2];
            int myidx = 0;
            if (lane < 8) myidx = nidx[(size_t)p * KNN + kh * 8 + lane];
            const uint32_t rowbase = (uint32_t)(pt1 * 32 + kh * 16);

            // ---- pass B: pre-split features, channel rows 64+lane, 96+lane
            {
                uint32_t gh[8], gl[8];
#pragma unroll
                for (int k2 = 0; k2 < 8; k2 += 2) {
                    const int id0 = __shfl_sync(0xffffffffu, myidx, k2);
                    const int id1 = __shfl_sync(0xffffffffu, myidx, k2 + 1);
                    const uint32_t* x0 = g_xtp + ((size_t)bb * NPTS + id0) * CIN;
                    const uint32_t* x1 = g_xtp + ((size_t)bb * NPTS + id1) * CIN;
                    const uint32_t a0 = x0[lane],      a1 = x1[lane];
                    const uint32_t b0 = x0[lane + 32], b1 = x1[lane + 32];
                    gh[k2 >> 1]       = __byte_perm(a0, a1, 0x5410);
                    gl[k2 >> 1]       = __byte_perm(a0, a1, 0x7632);
                    gh[4 + (k2 >> 1)] = __byte_perm(b0, b1, 0x5410);
                    gl[4 + (k2 >> 1)] = __byte_perm(b0, b1, 0x7632);
                }
                const uint32_t r0 = frow(64 + lane) + rowbase;
                const uint32_t r1 = frow(96 + lane) + rowbase;
                *(uint4*)(sFhi + r0) = make_uint4(gh[0], gh[1], gh[2], gh[3]);
                *(uint4*)(sFlo + r0) = make_uint4(gl[0], gl[1], gl[2], gl[3]);
                *(uint4*)(sFhi + r1) = make_uint4(gh[4], gh[5], gh[6], gh[7]);
                *(uint4*)(sFlo + r1) = make_uint4(gl[4], gl[5], gl[6], gl[7]);
            }
            // ---- pass A: rel-MLP, channel rows lane, lane+32
            {
                uint32_t gh[8], gl[8];
#pragma unroll
                for (int k2 = 0; k2 < 8; k2 += 2) {
                    float ra[2], rb[2];
#pragma unroll
                    for (int s = 0; s < 2; ++s) {
                        const int id = __shfl_sync(0xffffffffu, myidx, k2 + s);
                        const float nx = posB[id * 3 + 0];
                        const float ny = posB[id * 3 + 1];
                        const float nz = posB[id * 3 + 2];
                        const float rx = nx - cx, ry = ny - cy, rz = nz - cz;
                        const float d  = sqrtf(rx * rx + ry * ry + rz * rz);
                        const float enc[10] = {cx, cy, cz, nx, ny, nz, rx, ry, rz, d};
                        float a0 = sbrel[lane];
                        float a1 = sbrel[lane + 32];
#pragma unroll
                        for (int e = 0; e < 10; ++e) {
                            a0 = fmaf(enc[e], sWrel[e * DREL + lane],      a0);
                            a1 = fmaf(enc[e], sWrel[e * DREL + lane + 32], a1);
                        }
                        ra[s] = fmaxf(a0, 0.0f);
                        rb[s] = fmaxf(a1, 0.0f);
                    }
                    pack_pair(ra[0], ra[1], gh[k2 >> 1],       gl[k2 >> 1]);
                    pack_pair(rb[0], rb[1], gh[4 + (k2 >> 1)], gl[4 + (k2 >> 1)]);
                }
                const uint32_t r0 = frow(lane) + rowbase;
                const uint32_t r1 = frow(lane + 32) + rowbase;
                *(uint4*)(sFhi + r0) = make_uint4(gh[0], gh[1], gh[2], gh[3]);
                *(uint4*)(sFlo + r0) = make_uint4(gl[0], gl[1], gl[2], gl[3]);
                *(uint4*)(sFhi + r1) = make_uint4(gh[4], gh[5], gh[6], gh[7]);
                *(uint4*)(sFlo + r1) = make_uint4(gl[4], gl[5], gl[6], gl[7]);
            }
        }
        __syncthreads();

        // ================= phase 2: MMA scores + softmax + agg ============
        // two points in flight per iteration for ILP
#pragma unroll 1
        for (int pp = 0; pp < 4; pp += 2) {
            const int ptX = pbase + pp;
            const int ptY = ptX + 1;
            const uint32_t colX = (uint32_t)ptX * 32;
            const uint32_t colY = colX + 32;
            // per point: 2 n-chunk accumulators (3-MMA chain each)
            float dAX[4] = {0.f, 0.f, 0.f, 0.f};
            float dBX[4] = {0.f, 0.f, 0.f, 0.f};
            float dAY[4] = {0.f, 0.f, 0.f, 0.f};
            float dBY[4] = {0.f, 0.f, 0.f, 0.f};
#pragma unroll
            for (int cc = 0; cc < 8; ++cc) {
                uint32_t bhX[4], blX[4], bhY[4], blY[4];
                LDSM_X4_T(bhX, rowB[cc] + colX);
                LDSM_X4_T(bhY, rowB[cc] + colY);
                LDSM_X4_T(blX, rowB[cc] + colX + F_TILE);
                LDSM_X4_T(blY, rowB[cc] + colY + F_TILE);
                MMA_BF16(dAX, Ahi[cc], bhX[0], bhX[1]);
                MMA_BF16(dBX, Ahi[cc], bhX[2], bhX[3]);
                MMA_BF16(dAY, Ahi[cc], bhY[0], bhY[1]);
                MMA_BF16(dBY, Ahi[cc], bhY[2], bhY[3]);
                MMA_BF16(dAX, Ahi[cc], blX[0], blX[1]);
                MMA_BF16(dBX, Ahi[cc], blX[2], blX[3]);
                MMA_BF16(dAY, Ahi[cc], blY[0], blY[1]);
                MMA_BF16(dBY, Ahi[cc], blY[2], blY[3]);
                MMA_BF16(dAX, Alo[cc], bhX[0], bhX[1]);
                MMA_BF16(dBX, Alo[cc], bhX[2], bhX[3]);
                MMA_BF16(dAY, Alo[cc], bhY[0], bhY[1]);
                MMA_BF16(dBY, Alo[cc], bhY[2], bhY[3]);
            }

#pragma unroll
            for (int s = 0; s < 2; ++s) {
                const int pt = s ? ptY : ptX;
                const uint32_t colb = s ? colY : colX;
                float* dA = s ? dAY : dAX;
                float* dB = s ? dBY : dBX;
                // rows: A -> channel 16*oc+gid, B -> +8. log2-domain scores.
                float vA[4] = {dA[0], dA[1], dB[0], dB[1]};
                float vB[4] = {dA[2], dA[3], dB[2], dB[3]};

                float mA = fmaxf(fmaxf(vA[0], vA[1]), fmaxf(vA[2], vA[3]));
                float mB = fmaxf(fmaxf(vB[0], vB[1]), fmaxf(vB[2], vB[3]));
                mA = fmaxf(mA, __shfl_xor_sync(0xffffffffu, mA, 1));
                mA = fmaxf(mA, __shfl_xor_sync(0xffffffffu, mA, 2));
                mB = fmaxf(mB, __shfl_xor_sync(0xffffffffu, mB, 1));
                mB = fmaxf(mB, __shfl_xor_sync(0xffffffffu, mB, 2));

                float sA = 0.f, sB = 0.f;
#pragma unroll
                for (int j = 0; j < 4; ++j) {
                    vA[j] = fast_exp2(vA[j] - mA); sA += vA[j];
                    vB[j] = fast_exp2(vB[j] - mB); sB += vB[j];
                }
                sA += __shfl_xor_sync(0xffffffffu, sA, 1);
                sA += __shfl_xor_sync(0xffffffffu, sA, 2);
                sB += __shfl_xor_sync(0xffffffffu, sB, 1);
                sB += __shfl_xor_sync(0xffffffffu, sB, 2);

                uint32_t fh[4], fl[4];
                LDSM_X4(fh, aggHiB + colb);
                LDSM_X4(fl, aggHiB + F_TILE + colb);

                float aggA, aggB;
                {
                    float2 h, l, f0, f1;
                    h = __bfloat1622float2(*(__nv_bfloat162*)&fh[0]);
                    l = __bfloat1622float2(*(__nv_bfloat162*)&fl[0]);
                    f0.x = h.x + l.x; f0.y = h.y + l.y;
                    h = __bfloat1622float2(*(__nv_bfloat162*)&fh[2]);
                    l = __bfloat1622float2(*(__nv_bfloat162*)&fl[2]);
                    f1.x = h.x + l.x; f1.y = h.y + l.y;
                    aggA = vA[0] * f0.x + vA[1] * f0.y + vA[2] * f1.x + vA[3] * f1.y;

                    h = __bfloat1622float2(*(__nv_bfloat162*)&fh[1]);
                    l = __bfloat1622float2(*(__nv_bfloat162*)&fl[1]);
                    f0.x = h.x + l.x; f0.y = h.y + l.y;
                    h = __bfloat1622float2(*(__nv_bfloat162*)&fh[3]);
                    l = __bfloat1622float2(*(__nv_bfloat162*)&fl[3]);
                    f1.x = h.x + l.x; f1.y = h.y + l.y;
                    aggB = vB[0] * f0.x + vB[1] * f0.y + vB[2] * f1.x + vB[3] * f1.y;
                }
                aggA += __shfl_xor_sync(0xffffffffu, aggA, 1);
                aggA += __shfl_xor_sync(0xffffffffu, aggA, 2);
                aggB += __shfl_xor_sync(0xffffffffu, aggB, 1);
                aggB += __shfl_xor_sync(0xffffffffu, aggB, 2);

                if (qid == 0) {
                    aggBuf[pt * AGG_STRIDE + 16 * oc + gid]     = aggA / sA;
                    aggBuf[pt * AGG_STRIDE + 16 * oc + gid + 8] = aggB / sB;
                }
            }
        }
        __syncthreads();

        // ================= phase 3: out-GEMM, float4, direct store ========
        // lane owns channel o3, points pA3 and pA3+4
        {
            const float* wrow = sWglobT + o3 * WG_STRIDE;
            const float* agA  = aggBuf + pA3 * AGG_STRIDE;
            const float* agB  = agA + 4 * AGG_STRIDE;
            float accA = sbglob[o3];
            float accB = accA;
#pragma unroll 8
            for (int c = 0; c < CMID; c += 4) {
                const float4 w4 = *(const float4*)(wrow + c);
                const float4 a4 = *(const float4*)(agA + c);
                const float4 b4 = *(const float4*)(agB + c);
                accA = fmaf(a4.x, w4.x, accA);
                accA = fmaf(a4.y, w4.y, accA);
                accA = fmaf(a4.z, w4.z, accA);
                accA = fmaf(a4.w, w4.w, accA);
                accB = fmaf(b4.x, w4.x, accB);
                accB = fmaf(b4.y, w4.y, accB);
                accB = fmaf(b4.z, w4.z, accB);
                accB = fmaf(b4.w, w4.w, accB);
            }
            accA = fmaxf(accA, 0.0f);
            accB = fmaxf(accB, 0.0f);
            float* ob = out + (size_t)bb * COUT * NPTS + (size_t)o3 * NPTS + n0;
            ob[pA3]     = accA;
            ob[pA3 + 4] = accB;
        }
        // no barrier: next phase 1 touches F only; sAgg is double-buffered
    }
}

// ---------------------------------------------------------------------------
extern "C" void kernel_launch(void* const* d_in, const int* in_sizes, int n_in,
                              void* d_out, int out_size) {
    const float* x     = (const float*)d_in[0];
    const float* pos   = (const float*)d_in[1];
    const int*   nidx  = (const int*)  d_in[2];
    const float* Wrel  = (const float*)d_in[3];
    const float* brel  = (const float*)d_in[4];
    const float* Watt  = (const float*)d_in[5];
    const float* Wglob = (const float*)d_in[6];
    const float* bglob = (const float*)d_in[7];
    float*       out   = (float*)d_out;

    transpose_x_kernel<<<dim3(NPTS / 32, CIN / 32, BATCH), dim3(32, 8)>>>(x);

    cudaFuncSetAttribute(randlanet_mma_kernel,
                         cudaFuncAttributeMaxDynamicSharedMemorySize, SMEM_BYTES);
    randlanet_mma_kernel<<<148, NTHREADS, SMEM_BYTES>>>(pos, nidx, Wrel, brel,
                                                        Watt, Wglob, bglob, out);
}

// round 12
// speedup vs baseline: 2.5490x; 1.1351x over previous
#include <cuda_runtime.h>
#include <cuda_bf16.h>
#include <cstdint>

// Problem constants
#define BATCH 4
#define NPTS  16384
#define KNN   16
#define CIN   64
#define DREL  64
#define CMID  128
#define COUT  128
#define GROUPS ((BATCH * NPTS) / 8)   // 8192 groups of 8 points
#define LOG2E 1.4426950408889634f
#define NTHREADS 512

// ---------------------------------------------------------------------------
// SMEM layout (bytes)
//   Fhi/Flo   : [128 c rows][128 pk cols] bf16, row stride 272B
//   WgThi/lo  : [128 o rows][128 c cols] bf16, row stride 272B (out-GEMM B)
//   Wrel fp32, brel, bglob
//   AggHi/Lo  : [2 parity][16 rows (8 pts used)][128 c] bf16, stride 272B
// ---------------------------------------------------------------------------
#define F_ROWSTRIDE 272
#define F_TILE      (128 * F_ROWSTRIDE + 64)     // 34880
#define OFF_FHI     0
#define OFF_FLO     F_TILE
#define OFF_WGH     (2 * F_TILE)                 // 69760
#define OFF_WGL     (OFF_WGH + F_TILE)           // 104640
#define OFF_WREL    (OFF_WGL + F_TILE)           // 139520
#define OFF_BREL    (OFF_WREL + 2560)
#define OFF_BGLOB   (OFF_BREL + 256)
#define OFF_AGG     (OFF_BGLOB + 512)            // 142848
#define AGG_TILE    (16 * F_ROWSTRIDE)           // 4352 (hi); lo at +4352
#define AGG_PAR     (2 * AGG_TILE)               // 8704 per parity
#define SMEM_BYTES  (OFF_AGG + 2 * AGG_PAR)      // 160256

// Scratch: packed bf16 hi/lo of transposed features: word = hi | (lo<<16)
__device__ uint32_t g_xtp[BATCH * NPTS * CIN];

// ---------------------------------------------------------------------------
static __device__ __forceinline__ uint32_t smem_u32(const void* p) {
    uint32_t a;
    asm("{ .reg .u64 t; cvta.to.shared.u64 t, %1; cvt.u32.u64 %0, t; }" : "=r"(a) : "l"(p));
    return a;
}

static __device__ __forceinline__ uint32_t frow(int c) {
    return (uint32_t)(c * F_ROWSTRIDE);
}

static __device__ __forceinline__ uint32_t pack_bf16x2(float v0, float v1) {
    __nv_bfloat162 h = __floats2bfloat162_rn(v0, v1);   // .x=v0 (low 16b)
    return *(uint32_t*)&h;
}

// split (v0,v1) into bf16 hi pair + bf16 lo-residual pair
static __device__ __forceinline__ void pack_pair(float v0, float v1,
                                                 uint32_t& h, uint32_t& l) {
    __nv_bfloat162 hh = __floats2bfloat162_rn(v0, v1);
    h = *(uint32_t*)&hh;
    l = pack_bf16x2(v0 - __bfloat162float(hh.x),
                    v1 - __bfloat162float(hh.y));
}

// fast 2^y : magic-rounding + degree-5 poly, FMA/ALU pipes only (no MUFU)
static __device__ __forceinline__ float fast_exp2(float y) {
    y = fmaxf(y, -80.0f);
    const float t = y + 12582912.0f;                    // 1.5 * 2^23
    const int   i = __float_as_int(t);
    const float f = y - (t - 12582912.0f);              // [-0.5, 0.5]
    float p = 0.00133335581f;
    p = fmaf(p, f, 0.00961812911f);
    p = fmaf(p, f, 0.05550410866f);
    p = fmaf(p, f, 0.24022650696f);
    p = fmaf(p, f, 0.69314718056f);
    p = fmaf(p, f, 1.0f);
    return __int_as_float(__float_as_int(p) + (i << 23));
}

#define MMA_BF16(D, A, B0, B1)                                                  \
    asm volatile("mma.sync.aligned.m16n8k16.row.col.f32.bf16.bf16.f32 "         \
                 "{%0,%1,%2,%3}, {%4,%5,%6,%7}, {%8,%9}, {%0,%1,%2,%3};"        \
                 : "+f"((D)[0]), "+f"((D)[1]), "+f"((D)[2]), "+f"((D)[3])       \
                 : "r"((A)[0]), "r"((A)[1]), "r"((A)[2]), "r"((A)[3]),          \
                   "r"(B0), "r"(B1))

#define LDSM_X4_T(R, ADDR)                                                      \
    asm volatile("ldmatrix.sync.aligned.m8n8.x4.trans.shared.b16 "              \
                 "{%0,%1,%2,%3}, [%4];"                                         \
                 : "=r"((R)[0]), "=r"((R)[1]), "=r"((R)[2]), "=r"((R)[3])       \
                 : "r"(ADDR))

#define LDSM_X4(R, ADDR)                                                        \
    asm volatile("ldmatrix.sync.aligned.m8n8.x4.shared.b16 {%0,%1,%2,%3}, [%4];"\
                 : "=r"((R)[0]), "=r"((R)[1]), "=r"((R)[2]), "=r"((R)[3])       \
                 : "r"(ADDR))

#define LDSM_X2(R0, R1, ADDR)                                                   \
    asm volatile("ldmatrix.sync.aligned.m8n8.x2.shared.b16 {%0,%1}, [%2];"      \
                 : "=r"(R0), "=r"(R1) : "r"(ADDR))

// ---------------------------------------------------------------------------
// Transpose + hi/lo split: x[B][64][N] -> g_xtp[B][N][64] (hi | lo<<16)
// ---------------------------------------------------------------------------
__global__ void transpose_x_kernel(const float* __restrict__ x) {
    __shared__ float tile[32][33];
    const int b  = blockIdx.z;
    const int c0 = blockIdx.y * 32;
    const int n0 = blockIdx.x * 32;
    const int tx = threadIdx.x, ty = threadIdx.y;   // (32, 8)

    const float* xb = x + (size_t)b * CIN * NPTS;
#pragma unroll
    for (int i = 0; i < 4; ++i)
        tile[ty + 8 * i][tx] = xb[(size_t)(c0 + ty + 8 * i) * NPTS + n0 + tx];
    __syncthreads();
    uint32_t* xo = g_xtp + ((size_t)b * NPTS + n0) * CIN;
#pragma unroll
    for (int i = 0; i < 4; ++i) {
        const float v = tile[tx][ty + 8 * i];
        const __nv_bfloat16 h = __float2bfloat16(v);
        const __nv_bfloat16 l = __float2bfloat16(v - __bfloat162float(h));
        const uint32_t w = (uint32_t)*(const uint16_t*)&h
                         | ((uint32_t)*(const uint16_t*)&l << 16);
        xo[(size_t)(ty + 8 * i) * CIN + c0 + tx] = w;
    }
}

// ---------------------------------------------------------------------------
// Fused kernel. 148 persistent CTAs x 512 threads (16 warps).
//   phase 1: warp (2p+h) builds k-half h of point p (register-packed rows,
//            conflict-free STS.128; x features pre-split from g_xtp)
//   phase 2: warp w: o-chunk (w&7) x points (w>>3)*4..+3, 2 points in
//            flight; 3-product bf16 hi/lo MMA; shfl softmax (FMA exp2);
//            agg written as bf16 hi/lo tile rows
//   phase 3: out-GEMM on tensor cores: A = agg tile (ldmatrix.x4),
//            B = WgT rows (ldmatrix.x2), 24 HMMA/warp, direct STG
// ---------------------------------------------------------------------------
__global__ __launch_bounds__(NTHREADS, 1)
void randlanet_mma_kernel(const float* __restrict__ pos,
                          const int*   __restrict__ nidx,
                          const float* __restrict__ Wrel,
                          const float* __restrict__ brel,
                          const float* __restrict__ Watt,
                          const float* __restrict__ Wglob,
                          const float* __restrict__ bglob,
                          float*       __restrict__ out) {
    extern __shared__ char smem[];
    char*  sFhi    = smem + OFF_FHI;
    char*  sFlo    = smem + OFF_FLO;
    float* sWrel   = (float*)(smem + OFF_WREL);
    float* sbrel   = (float*)(smem + OFF_BREL);
    float* sbglob  = (float*)(smem + OFF_BGLOB);

    const uint32_t uS   = smem_u32(smem);
    const uint32_t uFhi = uS + OFF_FHI;

    const int tid  = threadIdx.x;
    const int warp = tid >> 5;
    const int lane = tid & 31;
    const int gid  = lane >> 2;     // 0..7
    const int qid  = lane & 3;      // 0..3

    // phase-role indices
    const int pt1   = warp >> 1;        // phase 1: point
    const int kh    = warp & 1;         // phase 1: k-half
    const int oc    = warp & 7;         // phase 2: o-chunk
    const int pbase = (warp >> 3) * 4;  // phase 2: first point

    // ---- weights: WgT bf16 hi/lo tiles + Wrel/bias fp32 ----
    for (int i = tid; i < CMID * CMID; i += NTHREADS) {
        const int o = i >> 7, c = i & 127;
        const float v = Wglob[c * CMID + o];
        const __nv_bfloat16 h = __float2bfloat16(v);
        const __nv_bfloat16 l = __float2bfloat16(v - __bfloat162float(h));
        *(uint16_t*)(smem + OFF_WGH + frow(o) + 2 * c) = *(const uint16_t*)&h;
        *(uint16_t*)(smem + OFF_WGL + frow(o) + 2 * c) = *(const uint16_t*)&l;
    }
    for (int i = tid; i < 10 * DREL; i += NTHREADS) sWrel[i] = Wrel[i];
    if (tid < DREL) sbrel[tid]  = brel[tid];
    if (tid < COUT) sbglob[tid] = bglob[tid];

    // ---- W_att A-fragments for o-chunk oc, scaled by log2e, bf16 hi/lo ----
    uint32_t Ahi[8][4], Alo[8][4];
#pragma unroll
    for (int cc = 0; cc < 8; ++cc) {
#pragma unroll
        for (int r = 0; r < 4; ++r) {
            const int o = 16 * oc + gid + (r & 1) * 8;
            const int c = 16 * cc + 2 * qid + (r >> 1) * 8;
            const float v0 = Watt[c * CMID + o] * LOG2E;
            const float v1 = Watt[(c + 1) * CMID + o] * LOG2E;
            pack_pair(v0, v1, Ahi[cc][r], Alo[cc][r]);
        }
    }
    __syncthreads();

    // phase-2 ldmatrix bases
    uint32_t rowB[8];
#pragma unroll
    for (int cc = 0; cc < 8; ++cc)
        rowB[cc] = uFhi + frow(16 * cc + (lane & 15)) + ((lane & 16) ? 16u : 0u);
    const uint32_t aggHiB = uFhi + frow(16 * oc + (lane & 15))
                          + ((lane & 16) ? 16u : 0u);
    // phase-3 ldmatrix bases
    const uint32_t aAgg0 = uS + OFF_AGG + (uint32_t)(lane & 15) * F_ROWSTRIDE
                         + ((lane & 16) ? 16u : 0u);
    const uint32_t aWg   = uS + OFF_WGH
                         + (uint32_t)(8 * warp + (lane & 7)) * F_ROWSTRIDE
                         + ((lane & 8) ? 16u : 0u);
    const int oP = 8 * warp + 2 * qid;            // phase 3: output channels
    const float bias0 = bglob[oP];
    const float bias1 = bglob[oP + 1];

    for (int g = blockIdx.x; g < GROUPS; g += gridDim.x) {
        const int p0  = g * 8;
        const int par = (g / gridDim.x) & 1;
        const uint32_t aggBase = (uint32_t)(OFF_AGG + par * AGG_PAR);
        const int bb = p0 >> 14;            // NPTS = 16384
        const int n0 = p0 & (NPTS - 1);

        // ================= phase 1: build k-half of f for point pt1 =======
        {
            const int p = p0 + pt1;
            const int n = (p & (NPTS - 1));
            const float* posB = pos + (size_t)bb * NPTS * 3;
            const float cx = posB[n * 3 + 0];
            const float cy = posB[n * 3 + 1];
            const float cz = posB[n * 3 + 2];
            int myidx = 0;
            if (lane < 8) myidx = nidx[(size_t)p * KNN + kh * 8 + lane];
            const uint32_t rowbase = (uint32_t)(pt1 * 32 + kh * 16);

            // ---- pass B: pre-split features, channel rows 64+lane, 96+lane
            {
                uint32_t gh[8], gl[8];
#pragma unroll
                for (int k2 = 0; k2 < 8; k2 += 2) {
                    const int id0 = __shfl_sync(0xffffffffu, myidx, k2);
                    const int id1 = __shfl_sync(0xffffffffu, myidx, k2 + 1);
                    const uint32_t* x0 = g_xtp + ((size_t)bb * NPTS + id0) * CIN;
                    const uint32_t* x1 = g_xtp + ((size_t)bb * NPTS + id1) * CIN;
                    const uint32_t a0 = x0[lane],      a1 = x1[lane];
                    const uint32_t b0 = x0[lane + 32], b1 = x1[lane + 32];
                    gh[k2 >> 1]       = __byte_perm(a0, a1, 0x5410);
                    gl[k2 >> 1]       = __byte_perm(a0, a1, 0x7632);
                    gh[4 + (k2 >> 1)] = __byte_perm(b0, b1, 0x5410);
                    gl[4 + (k2 >> 1)] = __byte_perm(b0, b1, 0x7632);
                }
                const uint32_t r0 = frow(64 + lane) + rowbase;
                const uint32_t r1 = frow(96 + lane) + rowbase;
                *(uint4*)(sFhi + r0) = make_uint4(gh[0], gh[1], gh[2], gh[3]);
                *(uint4*)(sFlo + r0) = make_uint4(gl[0], gl[1], gl[2], gl[3]);
                *(uint4*)(sFhi + r1) = make_uint4(gh[4], gh[5], gh[6], gh[7]);
                *(uint4*)(sFlo + r1) = make_uint4(gl[4], gl[5], gl[6], gl[7]);
            }
            // ---- pass A: rel-MLP, channel rows lane, lane+32
            {
                uint32_t gh[8], gl[8];
#pragma unroll
                for (int k2 = 0; k2 < 8; k2 += 2) {
                    float ra[2], rb[2];
#pragma unroll
                    for (int s = 0; s < 2; ++s) {
                        const int id = __shfl_sync(0xffffffffu, myidx, k2 + s);
                        const float nx = posB[id * 3 + 0];
                        const float ny = posB[id * 3 + 1];
                        const float nz = posB[id * 3 + 2];
                        const float rx = nx - cx, ry = ny - cy, rz = nz - cz;
                        const float d  = sqrtf(rx * rx + ry * ry + rz * rz);
                        const float enc[10] = {cx, cy, cz, nx, ny, nz, rx, ry, rz, d};
                        float a0 = sbrel[lane];
                        float a1 = sbrel[lane + 32];
#pragma unroll
                        for (int e = 0; e < 10; ++e) {
                            a0 = fmaf(enc[e], sWrel[e * DREL + lane],      a0);
                            a1 = fmaf(enc[e], sWrel[e * DREL + lane + 32], a1);
                        }
                        ra[s] = fmaxf(a0, 0.0f);
                        rb[s] = fmaxf(a1, 0.0f);
                    }
                    pack_pair(ra[0], ra[1], gh[k2 >> 1],       gl[k2 >> 1]);
                    pack_pair(rb[0], rb[1], gh[4 + (k2 >> 1)], gl[4 + (k2 >> 1)]);
                }
                const uint32_t r0 = frow(lane) + rowbase;
                const uint32_t r1 = frow(lane + 32) + rowbase;
                *(uint4*)(sFhi + r0) = make_uint4(gh[0], gh[1], gh[2], gh[3]);
                *(uint4*)(sFlo + r0) = make_uint4(gl[0], gl[1], gl[2], gl[3]);
                *(uint4*)(sFhi + r1) = make_uint4(gh[4], gh[5], gh[6], gh[7]);
                *(uint4*)(sFlo + r1) = make_uint4(gl[4], gl[5], gl[6], gl[7]);
            }
        }
        __syncthreads();

        // ================= phase 2: MMA scores + softmax + agg ============
#pragma unroll 1
        for (int pp = 0; pp < 4; pp += 2) {
            const int ptX = pbase + pp;
            const int ptY = ptX + 1;
            const uint32_t colX = (uint32_t)ptX * 32;
            const uint32_t colY = colX + 32;
            float dAX[4] = {0.f, 0.f, 0.f, 0.f};
            float dBX[4] = {0.f, 0.f, 0.f, 0.f};
            float dAY[4] = {0.f, 0.f, 0.f, 0.f};
            float dBY[4] = {0.f, 0.f, 0.f, 0.f};
#pragma unroll
            for (int cc = 0; cc < 8; ++cc) {
                uint32_t bhX[4], blX[4], bhY[4], blY[4];
                LDSM_X4_T(bhX, rowB[cc] + colX);
                LDSM_X4_T(bhY, rowB[cc] + colY);
                LDSM_X4_T(blX, rowB[cc] + colX + F_TILE);
                LDSM_X4_T(blY, rowB[cc] + colY + F_TILE);
                MMA_BF16(dAX, Ahi[cc], bhX[0], bhX[1]);
                MMA_BF16(dBX, Ahi[cc], bhX[2], bhX[3]);
                MMA_BF16(dAY, Ahi[cc], bhY[0], bhY[1]);
                MMA_BF16(dBY, Ahi[cc], bhY[2], bhY[3]);
                MMA_BF16(dAX, Ahi[cc], blX[0], blX[1]);
                MMA_BF16(dBX, Ahi[cc], blX[2], blX[3]);
                MMA_BF16(dAY, Ahi[cc], blY[0], blY[1]);
                MMA_BF16(dBY, Ahi[cc], blY[2], blY[3]);
                MMA_BF16(dAX, Alo[cc], bhX[0], bhX[1]);
                MMA_BF16(dBX, Alo[cc], bhX[2], bhX[3]);
                MMA_BF16(dAY, Alo[cc], bhY[0], bhY[1]);
                MMA_BF16(dBY, Alo[cc], bhY[2], bhY[3]);
            }

#pragma unroll
            for (int s = 0; s < 2; ++s) {
                const int pt = s ? ptY : ptX;
                const uint32_t colb = s ? colY : colX;
                float* dA = s ? dAY : dAX;
                float* dB = s ? dBY : dBX;
                float vA[4] = {dA[0], dA[1], dB[0], dB[1]};
                float vB[4] = {dA[2], dA[3], dB[2], dB[3]};

                float mA = fmaxf(fmaxf(vA[0], vA[1]), fmaxf(vA[2], vA[3]));
                float mB = fmaxf(fmaxf(vB[0], vB[1]), fmaxf(vB[2], vB[3]));
                mA = fmaxf(mA, __shfl_xor_sync(0xffffffffu, mA, 1));
                mA = fmaxf(mA, __shfl_xor_sync(0xffffffffu, mA, 2));
                mB = fmaxf(mB, __shfl_xor_sync(0xffffffffu, mB, 1));
                mB = fmaxf(mB, __shfl_xor_sync(0xffffffffu, mB, 2));

                float sA = 0.f, sB = 0.f;
#pragma unroll
                for (int j = 0; j < 4; ++j) {
                    vA[j] = fast_exp2(vA[j] - mA); sA += vA[j];
                    vB[j] = fast_exp2(vB[j] - mB); sB += vB[j];
                }
                sA += __shfl_xor_sync(0xffffffffu, sA, 1);
                sA += __shfl_xor_sync(0xffffffffu, sA, 2);
                sB += __shfl_xor_sync(0xffffffffu, sB, 1);
                sB += __shfl_xor_sync(0xffffffffu, sB, 2);

                uint32_t fh[4], fl[4];
                LDSM_X4(fh, aggHiB + colb);
                LDSM_X4(fl, aggHiB + F_TILE + colb);

                float aggA, aggB;
                {
                    float2 h, l, f0, f1;
                    h = __bfloat1622float2(*(__nv_bfloat162*)&fh[0]);
                    l = __bfloat1622float2(*(__nv_bfloat162*)&fl[0]);
                    f0.x = h.x + l.x; f0.y = h.y + l.y;
                    h = __bfloat1622float2(*(__nv_bfloat162*)&fh[2]);
                    l = __bfloat1622float2(*(__nv_bfloat162*)&fl[2]);
                    f1.x = h.x + l.x; f1.y = h.y + l.y;
                    aggA = vA[0] * f0.x + vA[1] * f0.y + vA[2] * f1.x + vA[3] * f1.y;

                    h = __bfloat1622float2(*(__nv_bfloat162*)&fh[1]);
                    l = __bfloat1622float2(*(__nv_bfloat162*)&fl[1]);
                    f0.x = h.x + l.x; f0.y = h.y + l.y;
                    h = __bfloat1622float2(*(__nv_bfloat162*)&fh[3]);
                    l = __bfloat1622float2(*(__nv_bfloat162*)&fl[3]);
                    f1.x = h.x + l.x; f1.y = h.y + l.y;
                    aggB = vB[0] * f0.x + vB[1] * f0.y + vB[2] * f1.x + vB[3] * f1.y;
                }
                aggA += __shfl_xor_sync(0xffffffffu, aggA, 1);
                aggA += __shfl_xor_sync(0xffffffffu, aggA, 2);
                aggB += __shfl_xor_sync(0xffffffffu, aggB, 1);
                aggB += __shfl_xor_sync(0xffffffffu, aggB, 2);

                if (qid == 0) {
                    const float wA = aggA / sA;
                    const float wB = aggB / sB;
                    const uint32_t rb2 = aggBase + (uint32_t)pt * F_ROWSTRIDE;
                    const uint32_t c0b = (uint32_t)(16 * oc + gid) * 2;
                    const __nv_bfloat16 hA = __float2bfloat16(wA);
                    const __nv_bfloat16 lA = __float2bfloat16(wA - __bfloat162float(hA));
                    const __nv_bfloat16 hB = __float2bfloat16(wB);
                    const __nv_bfloat16 lB = __float2bfloat16(wB - __bfloat162float(hB));
                    *(uint16_t*)(smem + rb2 + c0b)                  = *(const uint16_t*)&hA;
                    *(uint16_t*)(smem + rb2 + AGG_TILE + c0b)       = *(const uint16_t*)&lA;
                    *(uint16_t*)(smem + rb2 + c0b + 16)             = *(const uint16_t*)&hB;
                    *(uint16_t*)(smem + rb2 + AGG_TILE + c0b + 16)  = *(const uint16_t*)&lB;
                }
            }
        }
        __syncthreads();

        // ================= phase 3: out-GEMM on tensor cores ==============
        // warp w: all 8 points x channels 8w..8w+7; D rows 8-15 ignored
        {
            const uint32_t aA = uS - uS + aAgg0 + (uint32_t)(par * AGG_PAR);
            float dP[4] = {0.f, 0.f, 0.f, 0.f};
            float dQ[4] = {0.f, 0.f, 0.f, 0.f};
#pragma unroll
            for (int cc = 0; cc < 8; ++cc) {
                uint32_t ah[4], al[4], bh0, bh1, bl0, bl1;
                LDSM_X4(ah, aA + cc * 32);
                LDSM_X4(al, aA + AGG_TILE + cc * 32);
                LDSM_X2(bh0, bh1, aWg + cc * 32);
                LDSM_X2(bl0, bl1, aWg + F_TILE + cc * 32);
                MMA_BF16(dP, ah, bh0, bh1);
                MMA_BF16(dQ, ah, bl0, bl1);
                MMA_BF16(dQ, al, bh0, bh1);
            }
            const float r0 = fmaxf(dP[0] + dQ[0] + bias0, 0.0f);
            const float r1 = fmaxf(dP[1] + dQ[1] + bias1, 0.0f);
            float* ob = out + (size_t)bb * COUT * NPTS + n0 + gid;
            ob[(size_t)oP * NPTS]       = r0;
            ob[(size_t)(oP + 1) * NPTS] = r1;
        }
        // no barrier: next phase 1 only writes F; phase-2 agg writes are
        // parity-buffered and gated by the post-phase-1 barrier
    }
}

// ---------------------------------------------------------------------------
extern "C" void kernel_launch(void* const* d_in, const int* in_sizes, int n_in,
                              void* d_out, int out_size) {
    const float* x     = (const float*)d_in[0];
    const float* pos   = (const float*)d_in[1];
    const int*   nidx  = (const int*)  d_in[2];
    const float* Wrel  = (const float*)d_in[3];
    const float* brel  = (const float*)d_in[4];
    const float* Watt  = (const float*)d_in[5];
    const float* Wglob = (const float*)d_in[6];
    const float* bglob = (const float*)d_in[7];
    float*       out   = (float*)d_out;

    transpose_x_kernel<<<dim3(NPTS / 32, CIN / 32, BATCH), dim3(32, 8)>>>(x);

    cudaFuncSetAttribute(randlanet_mma_kernel,
                         cudaFuncAttributeMaxDynamicSharedMemorySize, SMEM_BYTES);
    randlanet_mma_kernel<<<148, NTHREADS, SMEM_BYTES>>>(pos, nidx, Wrel, brel,
                                                        Watt, Wglob, bglob, out);
}